// round 6
// baseline (speedup 1.0000x reference)
#include <cuda_runtime.h>
#include <cuda_bf16.h>
#include <math.h>
#include <stdint.h>

#define B_    2
#define S_    2048
#define HID_  1024
#define NH_   16
#define HD_   64
#define MTOT  (B_ * S_)
#define WN_   (HID_ * HID_)

// ---------------- scratch (static device allocations) ----------------
__device__ int8_t g_A1[MTOT * HID_];
__device__ int8_t g_A2[MTOT * HID_];
__device__ float  g_sA[MTOT];
__device__ int8_t g_W1[4 * WN_];
__device__ int8_t g_W2[4 * WN_];
__device__ float  g_sW[4 * HID_];
__device__ int8_t g_C1[MTOT * HID_];
__device__ int8_t g_C2[MTOT * HID_];
__device__ float  g_sC[MTOT];
__device__ float  g_C [MTOT * HID_];
__device__ __nv_bfloat16 g_Qh[MTOT * HID_];
__device__ __nv_bfloat16 g_Ql[MTOT * HID_];
__device__ __nv_bfloat16 g_Kh[MTOT * HID_];
__device__ __nv_bfloat16 g_Kl[MTOT * HID_];
__device__ __nv_bfloat16 g_Vh[MTOT * HID_];
__device__ __nv_bfloat16 g_Vl[MTOT * HID_];

// ---------------- helpers (baseline PTX only) ----------------
__device__ __forceinline__ uint32_t smem_u32(const void* p) {
    uint32_t a;
    asm("{ .reg .u64 t; cvta.to.shared.u64 t, %1; cvt.u32.u64 %0, t; }" : "=r"(a) : "l"(p));
    return a;
}
__device__ __forceinline__ void ldsm_x4(uint32_t addr, uint32_t& r0, uint32_t& r1,
                                        uint32_t& r2, uint32_t& r3) {
    asm volatile("ldmatrix.sync.aligned.m8n8.x4.shared.b16 {%0,%1,%2,%3}, [%4];"
                 : "=r"(r0), "=r"(r1), "=r"(r2), "=r"(r3) : "r"(addr));
}
__device__ __forceinline__ void ldsm_x4_trans(uint32_t addr, uint32_t& r0, uint32_t& r1,
                                              uint32_t& r2, uint32_t& r3) {
    asm volatile("ldmatrix.sync.aligned.m8n8.x4.trans.shared.b16 {%0,%1,%2,%3}, [%4];"
                 : "=r"(r0), "=r"(r1), "=r"(r2), "=r"(r3) : "r"(addr));
}
__device__ __forceinline__ void mma16816(float* c, uint32_t a0, uint32_t a1,
                                         uint32_t a2, uint32_t a3,
                                         uint32_t b0, uint32_t b1) {
    asm volatile(
        "mma.sync.aligned.m16n8k16.row.col.f32.bf16.bf16.f32 "
        "{%0,%1,%2,%3}, {%4,%5,%6,%7}, {%8,%9}, {%0,%1,%2,%3};"
        : "+f"(c[0]), "+f"(c[1]), "+f"(c[2]), "+f"(c[3])
        : "r"(a0), "r"(a1), "r"(a2), "r"(a3), "r"(b0), "r"(b1));
}
__device__ __forceinline__ void mma_s8(int* c, uint32_t a0, uint32_t a1,
                                       uint32_t a2, uint32_t a3,
                                       uint32_t b0, uint32_t b1) {
    asm volatile(
        "mma.sync.aligned.m16n8k32.row.col.s32.s8.s8.s32 "
        "{%0,%1,%2,%3}, {%4,%5,%6,%7}, {%8,%9}, {%0,%1,%2,%3};"
        : "+r"(c[0]), "+r"(c[1]), "+r"(c[2]), "+r"(c[3])
        : "r"(a0), "r"(a1), "r"(a2), "r"(a3), "r"(b0), "r"(b1));
}
__device__ __forceinline__ void pack2_hilo(float a, float b, uint32_t& hi, uint32_t& lo) {
    __nv_bfloat16 ah = __float2bfloat16(a), bh = __float2bfloat16(b);
    float ar = a - __bfloat162float(ah), br = b - __bfloat162float(bh);
    __nv_bfloat16 al = __float2bfloat16(ar), bl = __float2bfloat16(br);
    hi = (uint32_t)(*(unsigned short*)&ah) | ((uint32_t)(*(unsigned short*)&bh) << 16);
    lo = (uint32_t)(*(unsigned short*)&al) | ((uint32_t)(*(unsigned short*)&bl) << 16);
}
#define CP16(dst, src) \
    asm volatile("cp.async.cg.shared.global [%0], [%1], 16;" :: "r"(dst), "l"(src))
#define CP_COMMIT() asm volatile("cp.async.commit_group;")
#define CP_WAIT1()  asm volatile("cp.async.wait_group 1;")

// ---------------- row-wise 2-level int8 quantization ----------------
// x = s*(a1 + a2/254),  s = rowmax/127
__device__ __forceinline__ void qrow_body(const float* __restrict__ src,
                                          int8_t* __restrict__ q1,
                                          int8_t* __restrict__ q2,
                                          float* __restrict__ sc,
                                          size_t row)
{
    __shared__ float wmax[8];
    const int t = threadIdx.x, lane = t & 31, w = t >> 5;
    float4 v = *(const float4*)(src + row * HID_ + t * 4);
    float m = fmaxf(fmaxf(fabsf(v.x), fabsf(v.y)), fmaxf(fabsf(v.z), fabsf(v.w)));
#pragma unroll
    for (int o = 16; o > 0; o >>= 1)
        m = fmaxf(m, __shfl_xor_sync(0xffffffffu, m, o));
    if (lane == 0) wmax[w] = m;
    __syncthreads();
    if (w == 0) {
        float mm = wmax[lane & 7];
#pragma unroll
        for (int o = 4; o > 0; o >>= 1)
            mm = fmaxf(mm, __shfl_xor_sync(0xffffffffu, mm, o));
        if (lane == 0) wmax[0] = mm;
    }
    __syncthreads();
    const float mx  = wmax[0];
    const float inv = mx > 0.f ? 127.f / mx : 0.f;
    float x[4] = {v.x, v.y, v.z, v.w};
    char a1[4], a2[4];
#pragma unroll
    for (int i = 0; i < 4; i++) {
        float u  = x[i] * inv;
        float f1 = rintf(u);
        float f2 = rintf((u - f1) * 254.f);
        a1[i] = (char)(int)f1;
        a2[i] = (char)(int)f2;
    }
    *(char4*)(q1 + row * HID_ + t * 4) = make_char4(a1[0], a1[1], a1[2], a1[3]);
    *(char4*)(q2 + row * HID_ + t * 4) = make_char4(a2[0], a2[1], a2[2], a2[3]);
    if (t == 0) sc[row] = mx * (1.f / 127.f);
}

__global__ __launch_bounds__(256) void qrow(
    const float* __restrict__ in, int8_t* __restrict__ q1,
    int8_t* __restrict__ q2, float* __restrict__ sc)
{
    qrow_body(in, q1, q2, sc, (size_t)blockIdx.x);
}

__global__ __launch_bounds__(256) void qrow4(
    const float* __restrict__ w0, const float* __restrict__ w1,
    const float* __restrict__ w2, const float* __restrict__ w3,
    int8_t* __restrict__ q1, int8_t* __restrict__ q2, float* __restrict__ sc)
{
    const int sel = blockIdx.x >> 10;
    const int r   = blockIdx.x & 1023;
    const float* src = sel == 0 ? w0 : (sel == 1 ? w1 : (sel == 2 ? w2 : w3));
    // write at global row blockIdx.x, but source row r of weight sel
    __shared__ float wmax[8];
    const int t = threadIdx.x, lane = t & 31, w = t >> 5;
    float4 v = *(const float4*)(src + (size_t)r * HID_ + t * 4);
    float m = fmaxf(fmaxf(fabsf(v.x), fabsf(v.y)), fmaxf(fabsf(v.z), fabsf(v.w)));
#pragma unroll
    for (int o = 16; o > 0; o >>= 1)
        m = fmaxf(m, __shfl_xor_sync(0xffffffffu, m, o));
    if (lane == 0) wmax[w] = m;
    __syncthreads();
    if (w == 0) {
        float mm = wmax[lane & 7];
#pragma unroll
        for (int o = 4; o > 0; o >>= 1)
            mm = fmaxf(mm, __shfl_xor_sync(0xffffffffu, mm, o));
        if (lane == 0) wmax[0] = mm;
    }
    __syncthreads();
    const float mx  = wmax[0];
    const float inv = mx > 0.f ? 127.f / mx : 0.f;
    float x[4] = {v.x, v.y, v.z, v.w};
    char a1[4], a2[4];
#pragma unroll
    for (int i = 0; i < 4; i++) {
        float u  = x[i] * inv;
        float f1 = rintf(u);
        float f2 = rintf((u - f1) * 254.f);
        a1[i] = (char)(int)f1;
        a2[i] = (char)(int)f2;
    }
    const size_t grow = (size_t)blockIdx.x;
    *(char4*)(q1 + grow * HID_ + t * 4) = make_char4(a1[0], a1[1], a1[2], a1[3]);
    *(char4*)(q2 + grow * HID_ + t * 4) = make_char4(a2[0], a2[1], a2[2], a2[3]);
    if (t == 0) sc[grow] = mx * (1.f / 127.f);
}

// ============================================================
// int8 tensor-core GEMM: C[M,N] = deq(A @ W^T) + bias, x oscale
// A = sA*(A1 + A2/254), W = sW*(W1 + W2/254)
// C = sA*sW*(A1W1 + (A2W1 + A1W2)/254) + bias
// CTA 128x128, BK=64, 256 threads, 2-stage cp.async.
// grid.z selects among up-to-3 (W, bias, dest) sets (QKV fused).
// ============================================================
#define I_LDAB 80                        // padded row stride (bytes) of int8 tiles
#define I_ARR  (128 * I_LDAB)            // 10240 bytes per array
#define I_STAGE_B (4 * I_ARR)            // 40960
#define I_SMEM_B (2 * I_STAGE_B)         // 81920

template<bool OUT16>
__global__ __launch_bounds__(256) void gemm_i8(
    const int8_t* __restrict__ A1, const int8_t* __restrict__ A2,
    const float* __restrict__ sA,
    const int8_t* __restrict__ W1b, const int8_t* __restrict__ W2b,
    const float* __restrict__ sWb,
    const float* __restrict__ bias0, const float* __restrict__ bias1,
    const float* __restrict__ bias2,
    float* __restrict__ Cout,
    __nv_bfloat16* __restrict__ Ch0, __nv_bfloat16* __restrict__ Cl0,
    __nv_bfloat16* __restrict__ Ch1, __nv_bfloat16* __restrict__ Cl1,
    __nv_bfloat16* __restrict__ Ch2, __nv_bfloat16* __restrict__ Cl2,
    int M, int N, int K, float osc0)
{
    extern __shared__ char smem[];
    const uint32_t sb = smem_u32(smem);

    const int z = blockIdx.z;
    const int8_t* W1 = W1b + (size_t)z * N * K;
    const int8_t* W2 = W2b + (size_t)z * N * K;
    const float*  sW = sWb + (size_t)z * N;
    const float* bias = z == 0 ? bias0 : (z == 1 ? bias1 : bias2);
    __nv_bfloat16* Ch = z == 0 ? Ch0 : (z == 1 ? Ch1 : Ch2);
    __nv_bfloat16* Cl = z == 0 ? Cl0 : (z == 1 ? Cl1 : Cl2);
    const float oscale = z == 0 ? osc0 : 1.0f;

    const int t    = threadIdx.x;
    const int lane = t & 31;
    const int wid  = t >> 5;
    const int wm   = (wid & 1) * 64;
    const int wn   = (wid >> 1) * 32;
    const int bm   = blockIdx.y * 128;
    const int bn   = blockIdx.x * 128;

    int d1[4][4][4], d23[4][4][4];
#pragma unroll
    for (int i = 0; i < 4; i++)
#pragma unroll
        for (int j = 0; j < 4; j++)
#pragma unroll
            for (int r = 0; r < 4; r++) { d1[i][j][r] = 0; d23[i][j][r] = 0; }

    // ldmatrix addresses (b16 view of int8 tiles: 40 b16 cols = 80B stride)
    const uint32_t aOff = (uint32_t)((wm + (lane & 15)) * I_LDAB + (lane >> 4) * 16);
    const uint32_t bOff = (uint32_t)((wn + (lane >> 4) * 8 + (lane & 7)) * I_LDAB
                                     + ((lane >> 3) & 1) * 16);

#define I_LOAD(s, k0) do {                                                       \
        uint32_t st = sb + (uint32_t)(s) * I_STAGE_B;                            \
        _Pragma("unroll")                                                        \
        for (int i2 = 0; i2 < 2; i2++) {                                         \
            int c2  = t + 256 * i2;                                              \
            int r   = c2 >> 2;                                                   \
            int col = (c2 & 3) * 16;                                             \
            uint32_t so = (uint32_t)(r * I_LDAB + col);                          \
            size_t ga = (size_t)(bm + r) * K + (k0) + col;                       \
            size_t gb = (size_t)(bn + r) * K + (k0) + col;                       \
            CP16(st + 0 * I_ARR + so, A1 + ga);                                  \
            CP16(st + 1 * I_ARR + so, A2 + ga);                                  \
            CP16(st + 2 * I_ARR + so, W1 + gb);                                  \
            CP16(st + 3 * I_ARR + so, W2 + gb);                                  \
        }                                                                        \
    } while (0)

    const int NK = K / 64;
    I_LOAD(0, 0);
    CP_COMMIT();

    for (int it = 0; it < NK; it++) {
        if (it + 1 < NK) I_LOAD((it + 1) & 1, (it + 1) * 64);
        CP_COMMIT();
        CP_WAIT1();
        __syncthreads();

        const uint32_t st  = sb + (uint32_t)(it & 1) * I_STAGE_B;
        const uint32_t a1B = st;
        const uint32_t a2B = st + 1 * I_ARR;
        const uint32_t w1B = st + 2 * I_ARR;
        const uint32_t w2B = st + 3 * I_ARR;

#pragma unroll
        for (int ks = 0; ks < 2; ks++) {
            const uint32_t kb = ks * 32;   // 32 bytes = k32 step
            uint32_t bw1[8], bw2[8];
#pragma unroll
            for (int pr = 0; pr < 2; pr++) {
                uint32_t ba = bOff + (uint32_t)(pr * 16 * I_LDAB) + kb;
                ldsm_x4(w1B + ba, bw1[pr*4+0], bw1[pr*4+1], bw1[pr*4+2], bw1[pr*4+3]);
                ldsm_x4(w2B + ba, bw2[pr*4+0], bw2[pr*4+1], bw2[pr*4+2], bw2[pr*4+3]);
            }
#pragma unroll
            for (int mt = 0; mt < 4; mt++) {
                uint32_t aa = aOff + (uint32_t)(mt * 16 * I_LDAB) + kb;
                uint32_t a1f[4], a2f[4];
                ldsm_x4(a1B + aa, a1f[0], a1f[1], a1f[2], a1f[3]);
                ldsm_x4(a2B + aa, a2f[0], a2f[1], a2f[2], a2f[3]);
#pragma unroll
                for (int nt = 0; nt < 4; nt++) {
                    const int pr = nt >> 1, hf = (nt & 1) * 2;
                    uint32_t b0 = bw1[pr*4 + hf], b1 = bw1[pr*4 + hf + 1];
                    uint32_t c0 = bw2[pr*4 + hf], c1 = bw2[pr*4 + hf + 1];
                    mma_s8(d1[mt][nt],  a1f[0], a1f[1], a1f[2], a1f[3], b0, b1);
                    mma_s8(d23[mt][nt], a2f[0], a2f[1], a2f[2], a2f[3], b0, b1);
                    mma_s8(d23[mt][nt], a1f[0], a1f[1], a1f[2], a1f[3], c0, c1);
                }
            }
        }
        __syncthreads();
    }

    const float r254 = 1.0f / 254.0f;
#pragma unroll
    for (int mt = 0; mt < 4; mt++) {
#pragma unroll
        for (int nt = 0; nt < 4; nt++) {
            int row = bm + wm + mt * 16 + (lane >> 2);
            int col = bn + wn + nt * 8 + (lane & 3) * 2;
            float sa0 = sA[row], sa1 = sA[row + 8];
            float sw0 = sW[col], sw1 = sW[col + 1];
            float2 bvv = *(const float2*)&bias[col];
            float v0x = (((float)d1[mt][nt][0] + (float)d23[mt][nt][0] * r254) * sa0 * sw0 + bvv.x) * oscale;
            float v0y = (((float)d1[mt][nt][1] + (float)d23[mt][nt][1] * r254) * sa0 * sw1 + bvv.y) * oscale;
            float v1x = (((float)d1[mt][nt][2] + (float)d23[mt][nt][2] * r254) * sa1 * sw0 + bvv.x) * oscale;
            float v1y = (((float)d1[mt][nt][3] + (float)d23[mt][nt][3] * r254) * sa1 * sw1 + bvv.y) * oscale;
            if (OUT16) {
                uint32_t h0, l0, h1, l1;
                pack2_hilo(v0x, v0y, h0, l0);
                pack2_hilo(v1x, v1y, h1, l1);
                *(uint32_t*)&Ch[(size_t)row * N + col] = h0;
                *(uint32_t*)&Cl[(size_t)row * N + col] = l0;
                *(uint32_t*)&Ch[(size_t)(row + 8) * N + col] = h1;
                *(uint32_t*)&Cl[(size_t)(row + 8) * N + col] = l1;
            } else {
                *(float2*)&Cout[(size_t)row * N + col] = make_float2(v0x, v0y);
                *(float2*)&Cout[(size_t)(row + 8) * N + col] = make_float2(v1x, v1y);
            }
        }
    }
}

// ============================================================
// Tensor-core flash ConsMax attention (bf16 hi/lo 3-MMA),
// cp.async double-buffered. 64 q-rows/CTA, Bc=64.
// Q pre-scaled by 1/8. Outputs fp32 C.
// ============================================================
#define LDV 72
#define A_AS (64 * LDV)
#define A_STAGE_B (4 * A_AS * 2)
#define A_MASK_OFF (2 * A_STAGE_B)
#define A_SMEM_B (A_MASK_OFF + 2 * 256)

__global__ __launch_bounds__(128) void consmax_attn_mma(
    const __nv_bfloat16* __restrict__ Qh, const __nv_bfloat16* __restrict__ Ql,
    const __nv_bfloat16* __restrict__ Kh, const __nv_bfloat16* __restrict__ Kl,
    const __nv_bfloat16* __restrict__ Vh, const __nv_bfloat16* __restrict__ Vl,
    const float* __restrict__ mask, const float* __restrict__ gamma,
    float* __restrict__ Ctx)
{
    extern __shared__ char smem[];
    const uint32_t sb = smem_u32(smem);

    const int qb = blockIdx.x, h = blockIdx.y, b = blockIdx.z;
    const int t = threadIdx.x, lane = t & 31, w = t >> 5;
    const int row0 = b * S_ + qb * 64;

    {
        int r = t >> 1, half = t & 1;
        const size_t g = (size_t)(row0 + r) * HID_ + h * HD_ + half * 32;
        char* d0 = smem + (r * LDV + half * 32) * 2;
#pragma unroll
        for (int i = 0; i < 4; i++) {
            *(uint4*)(d0 + i * 16)            = *(const uint4*)(Qh + g + i * 8);
            *(uint4*)(d0 + A_AS * 2 + i * 16) = *(const uint4*)(Ql + g + i * 8);
        }
    }
    __syncthreads();
    uint32_t qh[4][4], ql[4][4];
#pragma unroll
    for (int ks = 0; ks < 4; ks++) {
        uint32_t addr = (uint32_t)(((w * 16 + (lane & 15)) * LDV + ks * 16 + (lane >> 4) * 8) * 2);
        ldsm_x4(sb + addr,            qh[ks][0], qh[ks][1], qh[ks][2], qh[ks][3]);
        ldsm_x4(sb + A_AS * 2 + addr, ql[ks][0], ql[ks][1], ql[ks][2], ql[ks][3]);
    }
    __syncthreads();

    float m0 = -1e30f, m1 = -1e30f;
    float O[8][4];
#pragma unroll
    for (int nt = 0; nt < 8; nt++)
#pragma unroll
        for (int r = 0; r < 4; r++) O[nt][r] = 0.0f;

#define A_LOAD(s, j0) do {                                                        \
        uint32_t st = sb + (uint32_t)(s) * A_STAGE_B;                             \
        int r = t >> 1, half = t & 1;                                             \
        const size_t g = (size_t)(b * S_ + (j0) + r) * HID_ + h * HD_ + half * 32;\
        uint32_t so = (uint32_t)((r * LDV + half * 32) * 2);                      \
        _Pragma("unroll")                                                         \
        for (int i2 = 0; i2 < 4; i2++) {                                          \
            CP16(st + 0 * A_AS * 2 + so + i2 * 16, Kh + g + i2 * 8);              \
            CP16(st + 1 * A_AS * 2 + so + i2 * 16, Kl + g + i2 * 8);              \
            CP16(st + 2 * A_AS * 2 + so + i2 * 16, Vh + g + i2 * 8);              \
            CP16(st + 3 * A_AS * 2 + so + i2 * 16, Vl + g + i2 * 8);              \
        }                                                                         \
        if (t < 16)                                                               \
            CP16(sb + A_MASK_OFF + (uint32_t)(s) * 256 + t * 16,                  \
                 mask + (size_t)b * S_ + (j0) + t * 4);                           \
    } while (0)

    const int NCH = S_ / 64;
    A_LOAD(0, 0);
    CP_COMMIT();

    for (int it = 0; it < NCH; it++) {
        if (it + 1 < NCH) A_LOAD((it + 1) & 1, (it + 1) * 64);
        CP_COMMIT();
        CP_WAIT1();
        __syncthreads();

        const uint32_t st  = sb + (uint32_t)(it & 1) * A_STAGE_B;
        const uint32_t khB = st;
        const uint32_t klB = st + 1 * A_AS * 2;
        const uint32_t vhB = st + 2 * A_AS * 2;
        const uint32_t vlB = st + 3 * A_AS * 2;
        const float* smask = (const float*)(smem + A_MASK_OFF + (it & 1) * 256);

        float sc[8][4];
#pragma unroll
        for (int nt = 0; nt < 8; nt++)
#pragma unroll
            for (int r = 0; r < 4; r++) sc[nt][r] = 0.0f;

#pragma unroll
        for (int ks = 0; ks < 4; ks++) {
            uint32_t bh[4][4], bl[4][4];
#pragma unroll
            for (int nb = 0; nb < 4; nb++) {
                uint32_t addr = (uint32_t)(((nb * 16 + (lane >> 4) * 8 + (lane & 7)) * LDV
                                            + ks * 16 + ((lane >> 3) & 1) * 8) * 2);
                ldsm_x4(khB + addr, bh[nb][0], bh[nb][1], bh[nb][2], bh[nb][3]);
                ldsm_x4(klB + addr, bl[nb][0], bl[nb][1], bl[nb][2], bl[nb][3]);
            }
#pragma unroll
            for (int nb = 0; nb < 4; nb++) {
                mma16816(sc[2*nb],   qh[ks][0], qh[ks][1], qh[ks][2], qh[ks][3], bh[nb][0], bh[nb][1]);
                mma16816(sc[2*nb],   ql[ks][0], ql[ks][1], ql[ks][2], ql[ks][3], bh[nb][0], bh[nb][1]);
                mma16816(sc[2*nb],   qh[ks][0], qh[ks][1], qh[ks][2], qh[ks][3], bl[nb][0], bl[nb][1]);
                mma16816(sc[2*nb+1], qh[ks][0], qh[ks][1], qh[ks][2], qh[ks][3], bh[nb][2], bh[nb][3]);
                mma16816(sc[2*nb+1], ql[ks][0], ql[ks][1], ql[ks][2], ql[ks][3], bh[nb][2], bh[nb][3]);
                mma16816(sc[2*nb+1], qh[ks][0], qh[ks][1], qh[ks][2], qh[ks][3], bl[nb][2], bl[nb][3]);
            }
        }

        float mn0 = m0, mn1 = m1;
#pragma unroll
        for (int nt = 0; nt < 8; nt++) {
            int col = nt * 8 + (lane & 3) * 2;
            float ma = smask[col], mb2 = smask[col + 1];
            sc[nt][0] += ma; sc[nt][1] += mb2;
            sc[nt][2] += ma; sc[nt][3] += mb2;
            mn0 = fmaxf(mn0, fmaxf(sc[nt][0], sc[nt][1]));
            mn1 = fmaxf(mn1, fmaxf(sc[nt][2], sc[nt][3]));
        }
        mn0 = fmaxf(mn0, __shfl_xor_sync(0xffffffffu, mn0, 1));
        mn0 = fmaxf(mn0, __shfl_xor_sync(0xffffffffu, mn0, 2));
        mn1 = fmaxf(mn1, __shfl_xor_sync(0xffffffffu, mn1, 1));
        mn1 = fmaxf(mn1, __shfl_xor_sync(0xffffffffu, mn1, 2));
        float f0 = __expf(m0 - mn0), f1 = __expf(m1 - mn1);
        m0 = mn0; m1 = mn1;

        uint32_t pah[4][4], pal[4][4];
#pragma unroll
        for (int ks = 0; ks < 4; ks++) {
            float p00 = __expf(sc[2*ks][0] - m0),   p01 = __expf(sc[2*ks][1] - m0);
            float p02 = __expf(sc[2*ks][2] - m1),   p03 = __expf(sc[2*ks][3] - m1);
            float p10 = __expf(sc[2*ks+1][0] - m0), p11 = __expf(sc[2*ks+1][1] - m0);
            float p12 = __expf(sc[2*ks+1][2] - m1), p13 = __expf(sc[2*ks+1][3] - m1);
            pack2_hilo(p00, p01, pah[ks][0], pal[ks][0]);
            pack2_hilo(p02, p03, pah[ks][1], pal[ks][1]);
            pack2_hilo(p10, p11, pah[ks][2], pal[ks][2]);
            pack2_hilo(p12, p13, pah[ks][3], pal[ks][3]);
        }

#pragma unroll
        for (int nt = 0; nt < 8; nt++) {
            O[nt][0] *= f0; O[nt][1] *= f0; O[nt][2] *= f1; O[nt][3] *= f1;
        }

#pragma unroll
        for (int ks = 0; ks < 4; ks++) {
            uint32_t vh[4][4], vl[4][4];
#pragma unroll
            for (int db = 0; db < 4; db++) {
                uint32_t addr = (uint32_t)(((ks * 16 + ((lane >> 3) & 1) * 8 + (lane & 7)) * LDV
                                            + db * 16 + (lane >> 4) * 8) * 2);
                ldsm_x4_trans(vhB + addr, vh[db][0], vh[db][1], vh[db][2], vh[db][3]);
                ldsm_x4_trans(vlB + addr, vl[db][0], vl[db][1], vl[db][2], vl[db][3]);
            }
#pragma unroll
            for (int db = 0; db < 4; db++) {
                mma16816(O[2*db],   pah[ks][0], pah[ks][1], pah[ks][2], pah[ks][3], vh[db][0], vh[db][1]);
                mma16816(O[2*db],   pal[ks][0], pal[ks][1], pal[ks][2], pal[ks][3], vh[db][0], vh[db][1]);
                mma16816(O[2*db],   pah[ks][0], pah[ks][1], pah[ks][2], pah[ks][3], vl[db][0], vl[db][1]);
                mma16816(O[2*db+1], pah[ks][0], pah[ks][1], pah[ks][2], pah[ks][3], vh[db][2], vh[db][3]);
                mma16816(O[2*db+1], pal[ks][0], pal[ks][1], pal[ks][2], pal[ks][3], vh[db][2], vh[db][3]);
                mma16816(O[2*db+1], pah[ks][0], pah[ks][1], pah[ks][2], pah[ks][3], vl[db][2], vl[db][3]);
            }
        }
        __syncthreads();
    }

    const float ig = 1.0f / gamma[0];
#pragma unroll
    for (int nt = 0; nt < 8; nt++) {
        int r = row0 + w * 16 + (lane >> 2);
        int col = h * HD_ + nt * 8 + (lane & 3) * 2;
        *(float2*)&Ctx[(size_t)r * HID_ + col]       = make_float2(O[nt][0] * ig, O[nt][1] * ig);
        *(float2*)&Ctx[(size_t)(r + 8) * HID_ + col] = make_float2(O[nt][2] * ig, O[nt][3] * ig);
    }
}

// ============================================================
// Launch
// ============================================================
extern "C" void kernel_launch(void* const* d_in, const int* in_sizes, int n_in,
                              void* d_out, int out_size)
{
    (void)in_sizes; (void)n_in; (void)out_size;
    const float* X    = (const float*)d_in[0];
    const float* mask = (const float*)d_in[1];
    const float* Wq   = (const float*)d_in[2];
    const float* bq   = (const float*)d_in[3];
    const float* Wk   = (const float*)d_in[4];
    const float* bk   = (const float*)d_in[5];
    const float* Wv   = (const float*)d_in[6];
    const float* bv   = (const float*)d_in[7];
    const float* Wo   = (const float*)d_in[8];
    const float* bo   = (const float*)d_in[9];
    const float* gamma = (const float*)d_in[11];   // beta (d_in[10]) cancels exactly
    float* out = (float*)d_out;

    int8_t *a1, *a2, *w1, *w2, *c1, *c2;
    float *sa, *sw, *scc, *cp;
    __nv_bfloat16 *qhp, *qlp, *khp, *klp, *vhp, *vlp;
    cudaGetSymbolAddress((void**)&a1, g_A1);
    cudaGetSymbolAddress((void**)&a2, g_A2);
    cudaGetSymbolAddress((void**)&sa, g_sA);
    cudaGetSymbolAddress((void**)&w1, g_W1);
    cudaGetSymbolAddress((void**)&w2, g_W2);
    cudaGetSymbolAddress((void**)&sw, g_sW);
    cudaGetSymbolAddress((void**)&c1, g_C1);
    cudaGetSymbolAddress((void**)&c2, g_C2);
    cudaGetSymbolAddress((void**)&scc, g_sC);
    cudaGetSymbolAddress((void**)&cp, g_C);
    cudaGetSymbolAddress((void**)&qhp, g_Qh);
    cudaGetSymbolAddress((void**)&qlp, g_Ql);
    cudaGetSymbolAddress((void**)&khp, g_Kh);
    cudaGetSymbolAddress((void**)&klp, g_Kl);
    cudaGetSymbolAddress((void**)&vhp, g_Vh);
    cudaGetSymbolAddress((void**)&vlp, g_Vl);

    cudaFuncSetAttribute(gemm_i8<true>,  cudaFuncAttributeMaxDynamicSharedMemorySize, I_SMEM_B);
    cudaFuncSetAttribute(gemm_i8<false>, cudaFuncAttributeMaxDynamicSharedMemorySize, I_SMEM_B);
    cudaFuncSetAttribute(consmax_attn_mma, cudaFuncAttributeMaxDynamicSharedMemorySize, A_SMEM_B);

    // 1) quantize activations + all 4 weights
    qrow<<<MTOT, 256>>>(X, a1, a2, sa);
    qrow4<<<4 * HID_, 256>>>(Wq, Wk, Wv, Wo, w1, w2, sw);

    // 2) fused QKV int8 GEMM (z: 0=Q scaled 1/8, 1=K, 2=V)
    dim3 gq(HID_ / 128, MTOT / 128, 3);
    gemm_i8<true><<<gq, 256, I_SMEM_B>>>(a1, a2, sa, w1, w2, sw,
                                         bq, bk, bv, nullptr,
                                         qhp, qlp, khp, klp, vhp, vlp,
                                         MTOT, HID_, HID_, 0.125f);

    // 3) attention -> fp32 C
    dim3 ga(S_ / 64, NH_, B_);
    consmax_attn_mma<<<ga, 256 / 2, A_SMEM_B>>>(qhp, qlp, khp, klp, vhp, vlp, mask, gamma, cp);

    // 4) quantize C, output projection int8 GEMM -> fp32 out
    qrow<<<MTOT, 256>>>(cp, c1, c2, scc);
    dim3 go(HID_ / 128, MTOT / 128, 1);
    gemm_i8<false><<<go, 256, I_SMEM_B>>>(c1, c2, scc, w1 + 3 * (size_t)WN_, w2 + 3 * (size_t)WN_,
                                          sw + 3 * HID_, bo, nullptr, nullptr,
                                          out, nullptr, nullptr, nullptr, nullptr, nullptr, nullptr,
                                          MTOT, HID_, HID_, 1.0f);
}

// round 7
// speedup vs baseline: 1.9381x; 1.9381x over previous
#include <cuda_runtime.h>
#include <cuda_bf16.h>
#include <math.h>
#include <stdint.h>

#define B_    2
#define S_    2048
#define HID_  1024
#define NH_   16
#define HD_   64
#define MTOT  (B_ * S_)
#define WN_   (HID_ * HID_)

// ---------------- scratch (static device allocations) ----------------
__device__ __nv_bfloat16 g_Xhi[MTOT * HID_];
__device__ __nv_bfloat16 g_Xlo[MTOT * HID_];
__device__ __nv_bfloat16 g_Whi[4 * WN_];
__device__ __nv_bfloat16 g_Wlo[4 * WN_];
__device__ __nv_bfloat16 g_Qh[MTOT * HID_];
__device__ __nv_bfloat16 g_Ql[MTOT * HID_];
__device__ __nv_bfloat16 g_Kh[MTOT * HID_];
__device__ __nv_bfloat16 g_Kl[MTOT * HID_];
__device__ __nv_bfloat16 g_Vh[MTOT * HID_];
__device__ __nv_bfloat16 g_Vl[MTOT * HID_];
__device__ __nv_bfloat16 g_Ch[MTOT * HID_];
__device__ __nv_bfloat16 g_Cl[MTOT * HID_];

// ---------------- helpers (baseline PTX only) ----------------
__device__ __forceinline__ uint32_t smem_u32(const void* p) {
    uint32_t a;
    asm("{ .reg .u64 t; cvta.to.shared.u64 t, %1; cvt.u32.u64 %0, t; }" : "=r"(a) : "l"(p));
    return a;
}
__device__ __forceinline__ void ldsm_x4(uint32_t addr, uint32_t& r0, uint32_t& r1,
                                        uint32_t& r2, uint32_t& r3) {
    asm volatile("ldmatrix.sync.aligned.m8n8.x4.shared.b16 {%0,%1,%2,%3}, [%4];"
                 : "=r"(r0), "=r"(r1), "=r"(r2), "=r"(r3) : "r"(addr));
}
__device__ __forceinline__ void ldsm_x4_trans(uint32_t addr, uint32_t& r0, uint32_t& r1,
                                              uint32_t& r2, uint32_t& r3) {
    asm volatile("ldmatrix.sync.aligned.m8n8.x4.trans.shared.b16 {%0,%1,%2,%3}, [%4];"
                 : "=r"(r0), "=r"(r1), "=r"(r2), "=r"(r3) : "r"(addr));
}
__device__ __forceinline__ void mma16816(float* c, uint32_t a0, uint32_t a1,
                                         uint32_t a2, uint32_t a3,
                                         uint32_t b0, uint32_t b1) {
    asm volatile(
        "mma.sync.aligned.m16n8k16.row.col.f32.bf16.bf16.f32 "
        "{%0,%1,%2,%3}, {%4,%5,%6,%7}, {%8,%9}, {%0,%1,%2,%3};"
        : "+f"(c[0]), "+f"(c[1]), "+f"(c[2]), "+f"(c[3])
        : "r"(a0), "r"(a1), "r"(a2), "r"(a3), "r"(b0), "r"(b1));
}
__device__ __forceinline__ void pack2_hilo(float a, float b, uint32_t& hi, uint32_t& lo) {
    __nv_bfloat16 ah = __float2bfloat16(a), bh = __float2bfloat16(b);
    float ar = a - __bfloat162float(ah), br = b - __bfloat162float(bh);
    __nv_bfloat16 al = __float2bfloat16(ar), bl = __float2bfloat16(br);
    hi = (uint32_t)(*(unsigned short*)&ah) | ((uint32_t)(*(unsigned short*)&bh) << 16);
    lo = (uint32_t)(*(unsigned short*)&al) | ((uint32_t)(*(unsigned short*)&bl) << 16);
}
#define CP16(dst, src) \
    asm volatile("cp.async.cg.shared.global [%0], [%1], 16;" :: "r"(dst), "l"(src))
#define CP_COMMIT() asm volatile("cp.async.commit_group;")
#define CP_WAIT1()  asm volatile("cp.async.wait_group 1;")

// ---------------- fp32 -> bf16 hi/lo split ----------------
__global__ __launch_bounds__(256) void cvt_split(
    const float* __restrict__ in, __nv_bfloat16* __restrict__ hi,
    __nv_bfloat16* __restrict__ lo, int n4)
{
    int i = blockIdx.x * blockDim.x + threadIdx.x;
    if (i >= n4) return;
    float4 v = ((const float4*)in)[i];
    float x[4] = {v.x, v.y, v.z, v.w};
    __nv_bfloat16 h[4], l[4];
#pragma unroll
    for (int j = 0; j < 4; j++) {
        h[j] = __float2bfloat16(x[j]);
        l[j] = __float2bfloat16(x[j] - __bfloat162float(h[j]));
    }
    ((ushort4*)hi)[i] = make_ushort4(*(unsigned short*)&h[0], *(unsigned short*)&h[1],
                                     *(unsigned short*)&h[2], *(unsigned short*)&h[3]);
    ((ushort4*)lo)[i] = make_ushort4(*(unsigned short*)&l[0], *(unsigned short*)&l[1],
                                     *(unsigned short*)&l[2], *(unsigned short*)&l[3]);
}

// ============================================================
// Tensor-core GEMM, cp.async double-buffered, bf16 hi/lo 3-MMA.
// grid.z selects among up to 3 (W, bias, dest) sets (QKV fused).
// C = (A @ W[z]^T + bias[z]) * (z==0 ? osc0 : 1)
// ============================================================
#define LDA 40
#define G_AS (128 * LDA)
#define G_STAGE_B (4 * G_AS * 2)
#define G_SMEM_B (2 * G_STAGE_B)

template<bool OUT16>
__global__ __launch_bounds__(256) void gemm_mma_bf16x3(
    const __nv_bfloat16* __restrict__ Ahi, const __nv_bfloat16* __restrict__ Alo,
    const __nv_bfloat16* __restrict__ Whib, const __nv_bfloat16* __restrict__ Wlob,
    const float* __restrict__ bias0, const float* __restrict__ bias1,
    const float* __restrict__ bias2,
    float* __restrict__ C,
    __nv_bfloat16* __restrict__ Ch0, __nv_bfloat16* __restrict__ Cl0,
    __nv_bfloat16* __restrict__ Ch1, __nv_bfloat16* __restrict__ Cl1,
    __nv_bfloat16* __restrict__ Ch2, __nv_bfloat16* __restrict__ Cl2,
    int M, int N, int K, float osc0)
{
    extern __shared__ char smem[];
    const uint32_t sb = smem_u32(smem);

    const int z = blockIdx.z;
    const __nv_bfloat16* Bhi = Whib + (size_t)z * WN_;
    const __nv_bfloat16* Blo = Wlob + (size_t)z * WN_;
    const float* bias = z == 0 ? bias0 : (z == 1 ? bias1 : bias2);
    __nv_bfloat16* Ch = z == 0 ? Ch0 : (z == 1 ? Ch1 : Ch2);
    __nv_bfloat16* Cl = z == 0 ? Cl0 : (z == 1 ? Cl1 : Cl2);
    const float oscale = z == 0 ? osc0 : 1.0f;

    const int t    = threadIdx.x;
    const int lane = t & 31;
    const int wid  = t >> 5;
    const int wm   = (wid & 1) * 64;
    const int wn   = (wid >> 1) * 32;
    const int bm   = blockIdx.y * 128;
    const int bn   = blockIdx.x * 128;

    float acc[4][4][4];
#pragma unroll
    for (int i = 0; i < 4; i++)
#pragma unroll
        for (int j = 0; j < 4; j++)
#pragma unroll
            for (int r = 0; r < 4; r++) acc[i][j][r] = 0.0f;

    const int lr = t >> 2;
    const int lc = (t & 3) * 8;

    const uint32_t aOff = (uint32_t)(((wm + (lane & 15)) * LDA + (lane >> 4) * 8) * 2);
    const uint32_t bOff = (uint32_t)(((wn + (lane >> 4) * 8 + (lane & 7)) * LDA + ((lane >> 3) & 1) * 8) * 2);

#define G_LOAD(s, k0) do {                                                        \
        uint32_t st = sb + (uint32_t)(s) * G_STAGE_B;                             \
        _Pragma("unroll")                                                         \
        for (int bch = 0; bch < 2; bch++) {                                       \
            int r = lr + bch * 64;                                                \
            size_t ga = (size_t)(bm + r) * K + (k0) + lc;                         \
            size_t gb = (size_t)(bn + r) * K + (k0) + lc;                         \
            uint32_t so = (uint32_t)((r * LDA + lc) * 2);                         \
            CP16(st + 0 * G_AS * 2 + so, Ahi + ga);                               \
            CP16(st + 1 * G_AS * 2 + so, Alo + ga);                               \
            CP16(st + 2 * G_AS * 2 + so, Bhi + gb);                               \
            CP16(st + 3 * G_AS * 2 + so, Blo + gb);                               \
        }                                                                         \
    } while (0)

    const int NK = K / 32;
    G_LOAD(0, 0);
    CP_COMMIT();

    for (int it = 0; it < NK; it++) {
        if (it + 1 < NK) G_LOAD((it + 1) & 1, (it + 1) * 32);
        CP_COMMIT();
        CP_WAIT1();
        __syncthreads();

        const uint32_t st   = sb + (uint32_t)(it & 1) * G_STAGE_B;
        const uint32_t aB   = st;
        const uint32_t alB  = st + 1 * G_AS * 2;
        const uint32_t bB   = st + 2 * G_AS * 2;
        const uint32_t blB  = st + 3 * G_AS * 2;

#pragma unroll
        for (int ks = 0; ks < 2; ks++) {
            const uint32_t kb = ks * 32;
            uint32_t bh[8], bl[8];
#pragma unroll
            for (int pr = 0; pr < 2; pr++) {
                uint32_t ba = bOff + (uint32_t)(pr * 16 * LDA * 2) + kb;
                ldsm_x4(bB + ba,  bh[pr*4+0], bh[pr*4+1], bh[pr*4+2], bh[pr*4+3]);
                ldsm_x4(blB + ba, bl[pr*4+0], bl[pr*4+1], bl[pr*4+2], bl[pr*4+3]);
            }
            uint32_t ah[4][4], al[4][4];
#pragma unroll
            for (int mt = 0; mt < 4; mt++) {
                uint32_t aa = aOff + (uint32_t)(mt * 16 * LDA * 2) + kb;
                ldsm_x4(aB + aa,  ah[mt][0], ah[mt][1], ah[mt][2], ah[mt][3]);
                ldsm_x4(alB + aa, al[mt][0], al[mt][1], al[mt][2], al[mt][3]);
            }
#pragma unroll
            for (int mt = 0; mt < 4; mt++) {
#pragma unroll
                for (int nt = 0; nt < 4; nt++) {
                    const int pr = nt >> 1, hf = (nt & 1) * 2;
                    uint32_t b0h = bh[pr*4 + hf], b1h = bh[pr*4 + hf + 1];
                    uint32_t b0l = bl[pr*4 + hf], b1l = bl[pr*4 + hf + 1];
                    mma16816(acc[mt][nt], ah[mt][0], ah[mt][1], ah[mt][2], ah[mt][3], b0h, b1h);
                    mma16816(acc[mt][nt], al[mt][0], al[mt][1], al[mt][2], al[mt][3], b0h, b1h);
                    mma16816(acc[mt][nt], ah[mt][0], ah[mt][1], ah[mt][2], ah[mt][3], b0l, b1l);
                }
            }
        }
        __syncthreads();
    }

#pragma unroll
    for (int mt = 0; mt < 4; mt++) {
#pragma unroll
        for (int nt = 0; nt < 4; nt++) {
            int row = bm + wm + mt * 16 + (lane >> 2);
            int col = bn + wn + nt * 8 + (lane & 3) * 2;
            float2 bvv = *(const float2*)&bias[col];
            float v0x = (acc[mt][nt][0] + bvv.x) * oscale, v0y = (acc[mt][nt][1] + bvv.y) * oscale;
            float v1x = (acc[mt][nt][2] + bvv.x) * oscale, v1y = (acc[mt][nt][3] + bvv.y) * oscale;
            if (OUT16) {
                uint32_t h0, l0, h1, l1;
                pack2_hilo(v0x, v0y, h0, l0);
                pack2_hilo(v1x, v1y, h1, l1);
                *(uint32_t*)&Ch[(size_t)row * N + col] = h0;
                *(uint32_t*)&Cl[(size_t)row * N + col] = l0;
                *(uint32_t*)&Ch[(size_t)(row + 8) * N + col] = h1;
                *(uint32_t*)&Cl[(size_t)(row + 8) * N + col] = l1;
            } else {
                *(float2*)&C[(size_t)row * N + col] = make_float2(v0x, v0y);
                *(float2*)&C[(size_t)(row + 8) * N + col] = make_float2(v1x, v1y);
            }
        }
    }
}

// ============================================================
// Tensor-core flash ConsMax attention, cp.async double-buffered.
// 128 q-rows/CTA, 8 warps (16 rows each), Bc=64.
// Q pre-scaled by 1/8 upstream; Q frags loaded straight from gmem.
// ============================================================
#define LDV 72
#define A_AS (64 * LDV)
#define A_STAGE_B (4 * A_AS * 2)
#define A_MASK_OFF (2 * A_STAGE_B)
#define A_SMEM_B (A_MASK_OFF + 2 * 256)

__global__ __launch_bounds__(256) void consmax_attn_mma(
    const __nv_bfloat16* __restrict__ Qh, const __nv_bfloat16* __restrict__ Ql,
    const __nv_bfloat16* __restrict__ Kh, const __nv_bfloat16* __restrict__ Kl,
    const __nv_bfloat16* __restrict__ Vh, const __nv_bfloat16* __restrict__ Vl,
    const float* __restrict__ mask, const float* __restrict__ gamma,
    __nv_bfloat16* __restrict__ Ch, __nv_bfloat16* __restrict__ Cl)
{
    extern __shared__ char smem[];
    const uint32_t sb = smem_u32(smem);

    const int qb = blockIdx.x, h = blockIdx.y, b = blockIdx.z;
    const int t = threadIdx.x, lane = t & 31, w = t >> 5;
    const int row0 = b * S_ + qb * 128;

    // ---- Q fragments straight from global (A-frag layout) ----
    uint32_t qh[4][4], ql[4][4];
    {
        const int fr = lane >> 2;           // 0..7
        const int fc = (lane & 3) * 2;      // 0,2,4,6
        const size_t base = (size_t)(row0 + w * 16 + fr) * HID_ + h * HD_ + fc;
#pragma unroll
        for (int ks = 0; ks < 4; ks++) {
            const size_t g = base + ks * 16;
            qh[ks][0] = *(const uint32_t*)(Qh + g);
            qh[ks][1] = *(const uint32_t*)(Qh + g + 8 * HID_);
            qh[ks][2] = *(const uint32_t*)(Qh + g + 8);
            qh[ks][3] = *(const uint32_t*)(Qh + g + 8 * HID_ + 8);
            ql[ks][0] = *(const uint32_t*)(Ql + g);
            ql[ks][1] = *(const uint32_t*)(Ql + g + 8 * HID_);
            ql[ks][2] = *(const uint32_t*)(Ql + g + 8);
            ql[ks][3] = *(const uint32_t*)(Ql + g + 8 * HID_ + 8);
        }
    }

    float m0 = -1e30f, m1 = -1e30f;
    float O[8][4];
#pragma unroll
    for (int nt = 0; nt < 8; nt++)
#pragma unroll
        for (int r = 0; r < 4; r++) O[nt][r] = 0.0f;

#define A_LOAD(s, j0) do {                                                        \
        uint32_t st = sb + (uint32_t)(s) * A_STAGE_B;                             \
        _Pragma("unroll")                                                         \
        for (int i2 = 0; i2 < 2; i2++) {                                          \
            int u = t + 256 * i2;                                                 \
            int r = u >> 3, seg = u & 7;                                          \
            const size_t g = (size_t)(b * S_ + (j0) + r) * HID_ + h * HD_ + seg * 8; \
            uint32_t so = (uint32_t)((r * LDV + seg * 8) * 2);                    \
            CP16(st + 0 * A_AS * 2 + so, Kh + g);                                 \
            CP16(st + 1 * A_AS * 2 + so, Kl + g);                                 \
            CP16(st + 2 * A_AS * 2 + so, Vh + g);                                 \
            CP16(st + 3 * A_AS * 2 + so, Vl + g);                                 \
        }                                                                         \
        if (t < 16)                                                               \
            CP16(sb + A_MASK_OFF + (uint32_t)(s) * 256 + t * 16,                  \
                 mask + (size_t)b * S_ + (j0) + t * 4);                           \
    } while (0)

    const int NCH = S_ / 64;
    A_LOAD(0, 0);
    CP_COMMIT();

    for (int it = 0; it < NCH; it++) {
        if (it + 1 < NCH) A_LOAD((it + 1) & 1, (it + 1) * 64);
        CP_COMMIT();
        CP_WAIT1();
        __syncthreads();

        const uint32_t st  = sb + (uint32_t)(it & 1) * A_STAGE_B;
        const uint32_t khB = st;
        const uint32_t klB = st + 1 * A_AS * 2;
        const uint32_t vhB = st + 2 * A_AS * 2;
        const uint32_t vlB = st + 3 * A_AS * 2;
        const float* smask = (const float*)(smem + A_MASK_OFF + (it & 1) * 256);

        // ---- S = Q K^T (3-MMA hi/lo) ----
        float sc[8][4];
#pragma unroll
        for (int nt = 0; nt < 8; nt++)
#pragma unroll
            for (int r = 0; r < 4; r++) sc[nt][r] = 0.0f;

#pragma unroll
        for (int ks = 0; ks < 4; ks++) {
            uint32_t bh[4][4], bl[4][4];
#pragma unroll
            for (int nb = 0; nb < 4; nb++) {
                uint32_t addr = (uint32_t)(((nb * 16 + (lane >> 4) * 8 + (lane & 7)) * LDV
                                            + ks * 16 + ((lane >> 3) & 1) * 8) * 2);
                ldsm_x4(khB + addr, bh[nb][0], bh[nb][1], bh[nb][2], bh[nb][3]);
                ldsm_x4(klB + addr, bl[nb][0], bl[nb][1], bl[nb][2], bl[nb][3]);
            }
#pragma unroll
            for (int nb = 0; nb < 4; nb++) {
                mma16816(sc[2*nb],   qh[ks][0], qh[ks][1], qh[ks][2], qh[ks][3], bh[nb][0], bh[nb][1]);
                mma16816(sc[2*nb],   ql[ks][0], ql[ks][1], ql[ks][2], ql[ks][3], bh[nb][0], bh[nb][1]);
                mma16816(sc[2*nb],   qh[ks][0], qh[ks][1], qh[ks][2], qh[ks][3], bl[nb][0], bl[nb][1]);
                mma16816(sc[2*nb+1], qh[ks][0], qh[ks][1], qh[ks][2], qh[ks][3], bh[nb][2], bh[nb][3]);
                mma16816(sc[2*nb+1], ql[ks][0], ql[ks][1], ql[ks][2], ql[ks][3], bh[nb][2], bh[nb][3]);
                mma16816(sc[2*nb+1], qh[ks][0], qh[ks][1], qh[ks][2], qh[ks][3], bl[nb][2], bl[nb][3]);
            }
        }

        // ---- mask + running rowmax ----
        float mn0 = m0, mn1 = m1;
#pragma unroll
        for (int nt = 0; nt < 8; nt++) {
            int col = nt * 8 + (lane & 3) * 2;
            float ma = smask[col], mb2 = smask[col + 1];
            sc[nt][0] += ma; sc[nt][1] += mb2;
            sc[nt][2] += ma; sc[nt][3] += mb2;
            mn0 = fmaxf(mn0, fmaxf(sc[nt][0], sc[nt][1]));
            mn1 = fmaxf(mn1, fmaxf(sc[nt][2], sc[nt][3]));
        }
        mn0 = fmaxf(mn0, __shfl_xor_sync(0xffffffffu, mn0, 1));
        mn0 = fmaxf(mn0, __shfl_xor_sync(0xffffffffu, mn0, 2));
        mn1 = fmaxf(mn1, __shfl_xor_sync(0xffffffffu, mn1, 1));
        mn1 = fmaxf(mn1, __shfl_xor_sync(0xffffffffu, mn1, 2));
        float f0 = __expf(m0 - mn0), f1 = __expf(m1 - mn1);
        m0 = mn0; m1 = mn1;

        // ---- P = exp(s - m), hi/lo split -> A-frags ----
        uint32_t pah[4][4], pal[4][4];
#pragma unroll
        for (int ks = 0; ks < 4; ks++) {
            float p00 = __expf(sc[2*ks][0] - m0),   p01 = __expf(sc[2*ks][1] - m0);
            float p02 = __expf(sc[2*ks][2] - m1),   p03 = __expf(sc[2*ks][3] - m1);
            float p10 = __expf(sc[2*ks+1][0] - m0), p11 = __expf(sc[2*ks+1][1] - m0);
            float p12 = __expf(sc[2*ks+1][2] - m1), p13 = __expf(sc[2*ks+1][3] - m1);
            pack2_hilo(p00, p01, pah[ks][0], pal[ks][0]);
            pack2_hilo(p02, p03, pah[ks][1], pal[ks][1]);
            pack2_hilo(p10, p11, pah[ks][2], pal[ks][2]);
            pack2_hilo(p12, p13, pah[ks][3], pal[ks][3]);
        }

#pragma unroll
        for (int nt = 0; nt < 8; nt++) {
            O[nt][0] *= f0; O[nt][1] *= f0; O[nt][2] *= f1; O[nt][3] *= f1;
        }

        // ---- O += P V (3-MMA hi/lo) ----
#pragma unroll
        for (int ks = 0; ks < 4; ks++) {
            uint32_t vh[4][4], vl[4][4];
#pragma unroll
            for (int db = 0; db < 4; db++) {
                uint32_t addr = (uint32_t)(((ks * 16 + ((lane >> 3) & 1) * 8 + (lane & 7)) * LDV
                                            + db * 16 + (lane >> 4) * 8) * 2);
                ldsm_x4_trans(vhB + addr, vh[db][0], vh[db][1], vh[db][2], vh[db][3]);
                ldsm_x4_trans(vlB + addr, vl[db][0], vl[db][1], vl[db][2], vl[db][3]);
            }
#pragma unroll
            for (int db = 0; db < 4; db++) {
                mma16816(O[2*db],   pah[ks][0], pah[ks][1], pah[ks][2], pah[ks][3], vh[db][0], vh[db][1]);
                mma16816(O[2*db],   pal[ks][0], pal[ks][1], pal[ks][2], pal[ks][3], vh[db][0], vh[db][1]);
                mma16816(O[2*db],   pah[ks][0], pah[ks][1], pah[ks][2], pah[ks][3], vl[db][0], vl[db][1]);
                mma16816(O[2*db+1], pah[ks][0], pah[ks][1], pah[ks][2], pah[ks][3], vh[db][2], vh[db][3]);
                mma16816(O[2*db+1], pal[ks][0], pal[ks][1], pal[ks][2], pal[ks][3], vh[db][2], vh[db][3]);
                mma16816(O[2*db+1], pah[ks][0], pah[ks][1], pah[ks][2], pah[ks][3], vl[db][2], vl[db][3]);
            }
        }
        __syncthreads();
    }

    // ---- epilogue ----
    const float ig = 1.0f / gamma[0];
#pragma unroll
    for (int nt = 0; nt < 8; nt++) {
        int r = row0 + w * 16 + (lane >> 2);
        int col = h * HD_ + nt * 8 + (lane & 3) * 2;
        uint32_t h0, l0, h1, l1;
        pack2_hilo(O[nt][0] * ig, O[nt][1] * ig, h0, l0);
        pack2_hilo(O[nt][2] * ig, O[nt][3] * ig, h1, l1);
        *(uint32_t*)&Ch[(size_t)r * HID_ + col] = h0;
        *(uint32_t*)&Cl[(size_t)r * HID_ + col] = l0;
        *(uint32_t*)&Ch[(size_t)(r + 8) * HID_ + col] = h1;
        *(uint32_t*)&Cl[(size_t)(r + 8) * HID_ + col] = l1;
    }
}

// ============================================================
// Launch
// ============================================================
extern "C" void kernel_launch(void* const* d_in, const int* in_sizes, int n_in,
                              void* d_out, int out_size)
{
    (void)in_sizes; (void)n_in; (void)out_size;
    const float* X    = (const float*)d_in[0];
    const float* mask = (const float*)d_in[1];
    const float* Wq   = (const float*)d_in[2];
    const float* bq   = (const float*)d_in[3];
    const float* Wk   = (const float*)d_in[4];
    const float* bk   = (const float*)d_in[5];
    const float* Wv   = (const float*)d_in[6];
    const float* bv   = (const float*)d_in[7];
    const float* Wo   = (const float*)d_in[8];
    const float* bo   = (const float*)d_in[9];
    const float* gamma = (const float*)d_in[11];   // beta (d_in[10]) cancels exactly
    float* out = (float*)d_out;

    __nv_bfloat16 *xhi, *xlo, *whi, *wlo, *qhp, *qlp, *khp, *klp, *vhp, *vlp, *chp, *clp;
    cudaGetSymbolAddress((void**)&xhi, g_Xhi);
    cudaGetSymbolAddress((void**)&xlo, g_Xlo);
    cudaGetSymbolAddress((void**)&whi, g_Whi);
    cudaGetSymbolAddress((void**)&wlo, g_Wlo);
    cudaGetSymbolAddress((void**)&qhp, g_Qh);
    cudaGetSymbolAddress((void**)&qlp, g_Ql);
    cudaGetSymbolAddress((void**)&khp, g_Kh);
    cudaGetSymbolAddress((void**)&klp, g_Kl);
    cudaGetSymbolAddress((void**)&vhp, g_Vh);
    cudaGetSymbolAddress((void**)&vlp, g_Vl);
    cudaGetSymbolAddress((void**)&chp, g_Ch);
    cudaGetSymbolAddress((void**)&clp, g_Cl);

    cudaFuncSetAttribute(gemm_mma_bf16x3<true>,  cudaFuncAttributeMaxDynamicSharedMemorySize, G_SMEM_B);
    cudaFuncSetAttribute(gemm_mma_bf16x3<false>, cudaFuncAttributeMaxDynamicSharedMemorySize, G_SMEM_B);
    cudaFuncSetAttribute(consmax_attn_mma,       cudaFuncAttributeMaxDynamicSharedMemorySize, A_SMEM_B);

    cvt_split<<<(MTOT * HID_ / 4 + 255) / 256, 256>>>(X,  xhi, xlo, MTOT * HID_ / 4);
    cvt_split<<<(WN_ / 4 + 255) / 256, 256>>>(Wq, whi + 0 * WN_, wlo + 0 * WN_, WN_ / 4);
    cvt_split<<<(WN_ / 4 + 255) / 256, 256>>>(Wk, whi + 1 * WN_, wlo + 1 * WN_, WN_ / 4);
    cvt_split<<<(WN_ / 4 + 255) / 256, 256>>>(Wv, whi + 2 * WN_, wlo + 2 * WN_, WN_ / 4);
    cvt_split<<<(WN_ / 4 + 255) / 256, 256>>>(Wo, whi + 3 * WN_, wlo + 3 * WN_, WN_ / 4);

    // fused QKV projection: z = 0(Q, x1/8), 1(K), 2(V)
    dim3 gq(HID_ / 128, MTOT / 128, 3);
    gemm_mma_bf16x3<true><<<gq, 256, G_SMEM_B>>>(xhi, xlo, whi, wlo,
                                                 bq, bk, bv, nullptr,
                                                 qhp, qlp, khp, klp, vhp, vlp,
                                                 MTOT, HID_, HID_, 0.125f);

    dim3 ga(S_ / 128, NH_, B_);        // (16, 16, 2)
    consmax_attn_mma<<<ga, 256, A_SMEM_B>>>(qhp, qlp, khp, klp, vhp, vlp, mask, gamma, chp, clp);

    dim3 go(HID_ / 128, MTOT / 128, 1);
    gemm_mma_bf16x3<false><<<go, 256, G_SMEM_B>>>(chp, clp, whi + 3 * (size_t)WN_, wlo + 3 * (size_t)WN_,
                                                  bo, nullptr, nullptr,
                                                  out, nullptr, nullptr, nullptr, nullptr, nullptr, nullptr,
                                                  MTOT, HID_, HID_, 1.0f);
}

// round 8
// speedup vs baseline: 2.0684x; 1.0673x over previous
#include <cuda_runtime.h>
#include <cuda_fp16.h>
#include <math.h>
#include <stdint.h>

#define B_    2
#define S_    2048
#define HID_  1024
#define NH_   16
#define HD_   64
#define MTOT  (B_ * S_)
#define WN_   (HID_ * HID_)

// ---------------- scratch (static device allocations) ----------------
__device__ __half g_Xhi[MTOT * HID_];
__device__ __half g_Xlo[MTOT * HID_];
__device__ __half g_Whi[4 * WN_];
__device__ __half g_Wlo[4 * WN_];
__device__ __half g_Qh[MTOT * HID_];
__device__ __half g_Ql[MTOT * HID_];
__device__ __half g_Kh[MTOT * HID_];
__device__ __half g_Vh[MTOT * HID_];
__device__ __half g_Vl[MTOT * HID_];
__device__ __half g_Ch[MTOT * HID_];
__device__ __half g_Cl[MTOT * HID_];

// ---------------- helpers (baseline PTX only) ----------------
__device__ __forceinline__ uint32_t smem_u32(const void* p) {
    uint32_t a;
    asm("{ .reg .u64 t; cvta.to.shared.u64 t, %1; cvt.u32.u64 %0, t; }" : "=r"(a) : "l"(p));
    return a;
}
__device__ __forceinline__ void ldsm_x4(uint32_t addr, uint32_t& r0, uint32_t& r1,
                                        uint32_t& r2, uint32_t& r3) {
    asm volatile("ldmatrix.sync.aligned.m8n8.x4.shared.b16 {%0,%1,%2,%3}, [%4];"
                 : "=r"(r0), "=r"(r1), "=r"(r2), "=r"(r3) : "r"(addr));
}
__device__ __forceinline__ void ldsm_x4_trans(uint32_t addr, uint32_t& r0, uint32_t& r1,
                                              uint32_t& r2, uint32_t& r3) {
    asm volatile("ldmatrix.sync.aligned.m8n8.x4.trans.shared.b16 {%0,%1,%2,%3}, [%4];"
                 : "=r"(r0), "=r"(r1), "=r"(r2), "=r"(r3) : "r"(addr));
}
__device__ __forceinline__ void mma16816(float* c, uint32_t a0, uint32_t a1,
                                         uint32_t a2, uint32_t a3,
                                         uint32_t b0, uint32_t b1) {
    asm volatile(
        "mma.sync.aligned.m16n8k16.row.col.f32.f16.f16.f32 "
        "{%0,%1,%2,%3}, {%4,%5,%6,%7}, {%8,%9}, {%0,%1,%2,%3};"
        : "+f"(c[0]), "+f"(c[1]), "+f"(c[2]), "+f"(c[3])
        : "r"(a0), "r"(a1), "r"(a2), "r"(a3), "r"(b0), "r"(b1));
}
__device__ __forceinline__ uint32_t pack_h2(float a, float b) {
    __half2 h = __floats2half2_rn(a, b);
    return *(uint32_t*)&h;
}
__device__ __forceinline__ void pack2_hilo(float a, float b, uint32_t& hi, uint32_t& lo) {
    __half2 h = __floats2half2_rn(a, b);
    float2 hf = __half22float2(h);
    __half2 l = __floats2half2_rn(a - hf.x, b - hf.y);
    hi = *(uint32_t*)&h;
    lo = *(uint32_t*)&l;
}
#define CP16(dst, src) \
    asm volatile("cp.async.cg.shared.global [%0], [%1], 16;" :: "r"(dst), "l"(src))
#define CP_COMMIT() asm volatile("cp.async.commit_group;")
#define CP_WAIT1()  asm volatile("cp.async.wait_group 1;")

// ---------------- fp32 -> fp16 hi/lo split ----------------
__global__ __launch_bounds__(256) void cvt_split(
    const float* __restrict__ in, __half* __restrict__ hi,
    __half* __restrict__ lo, int n4)
{
    int i = blockIdx.x * blockDim.x + threadIdx.x;
    if (i >= n4) return;
    float4 v = ((const float4*)in)[i];
    uint32_t h0, l0, h1, l1;
    pack2_hilo(v.x, v.y, h0, l0);
    pack2_hilo(v.z, v.w, h1, l1);
    ((uint2*)hi)[i] = make_uint2(h0, h1);
    ((uint2*)lo)[i] = make_uint2(l0, l1);
}

// fused 4-weight split (W arrays are WN_ elems each; n4per = WN_/4)
__global__ __launch_bounds__(256) void cvt_split4(
    const float* __restrict__ w0, const float* __restrict__ w1,
    const float* __restrict__ w2, const float* __restrict__ w3,
    __half* __restrict__ hi, __half* __restrict__ lo)
{
    const int n4per = WN_ / 4;
    int i = blockIdx.x * blockDim.x + threadIdx.x;
    int sel = i / n4per;
    int j   = i - sel * n4per;
    const float* src = sel == 0 ? w0 : (sel == 1 ? w1 : (sel == 2 ? w2 : w3));
    float4 v = ((const float4*)src)[j];
    uint32_t h0, l0, h1, l1;
    pack2_hilo(v.x, v.y, h0, l0);
    pack2_hilo(v.z, v.w, h1, l1);
    ((uint2*)hi)[i] = make_uint2(h0, h1);
    ((uint2*)lo)[i] = make_uint2(l0, l1);
}

// ============================================================
// Tensor-core GEMM, cp.async double-buffered, fp16 hi/lo 3-MMA.
// grid.z selects among up to 3 (W, bias, dest) sets (QKV fused).
// If the z-dest lo pointer is null -> single-fp16 output (K path).
// ============================================================
#define LDA 40
#define G_AS (128 * LDA)
#define G_STAGE_B (4 * G_AS * 2)
#define G_SMEM_B (2 * G_STAGE_B)

template<bool OUT16>
__global__ __launch_bounds__(256) void gemm_mma_f16x3(
    const __half* __restrict__ Ahi, const __half* __restrict__ Alo,
    const __half* __restrict__ Whib, const __half* __restrict__ Wlob,
    const float* __restrict__ bias0, const float* __restrict__ bias1,
    const float* __restrict__ bias2,
    float* __restrict__ C,
    __half* __restrict__ Ch0, __half* __restrict__ Cl0,
    __half* __restrict__ Ch1, __half* __restrict__ Cl1,
    __half* __restrict__ Ch2, __half* __restrict__ Cl2,
    int M, int N, int K, float osc0)
{
    extern __shared__ char smem[];
    const uint32_t sb = smem_u32(smem);

    const int z = blockIdx.z;
    const __half* Bhi = Whib + (size_t)z * WN_;
    const __half* Blo = Wlob + (size_t)z * WN_;
    const float* bias = z == 0 ? bias0 : (z == 1 ? bias1 : bias2);
    __half* Ch = z == 0 ? Ch0 : (z == 1 ? Ch1 : Ch2);
    __half* Cl = z == 0 ? Cl0 : (z == 1 ? Cl1 : Cl2);
    const float oscale = z == 0 ? osc0 : 1.0f;

    const int t    = threadIdx.x;
    const int lane = t & 31;
    const int wid  = t >> 5;
    const int wm   = (wid & 1) * 64;
    const int wn   = (wid >> 1) * 32;
    const int bm   = blockIdx.y * 128;
    const int bn   = blockIdx.x * 128;

    float acc[4][4][4];
#pragma unroll
    for (int i = 0; i < 4; i++)
#pragma unroll
        for (int j = 0; j < 4; j++)
#pragma unroll
            for (int r = 0; r < 4; r++) acc[i][j][r] = 0.0f;

    const int lr = t >> 2;
    const int lc = (t & 3) * 8;

    const uint32_t aOff = (uint32_t)(((wm + (lane & 15)) * LDA + (lane >> 4) * 8) * 2);
    const uint32_t bOff = (uint32_t)(((wn + (lane >> 4) * 8 + (lane & 7)) * LDA + ((lane >> 3) & 1) * 8) * 2);

#define G_LOAD(s, k0) do {                                                        \
        uint32_t st = sb + (uint32_t)(s) * G_STAGE_B;                             \
        _Pragma("unroll")                                                         \
        for (int bch = 0; bch < 2; bch++) {                                       \
            int r = lr + bch * 64;                                                \
            size_t ga = (size_t)(bm + r) * K + (k0) + lc;                         \
            size_t gb = (size_t)(bn + r) * K + (k0) + lc;                         \
            uint32_t so = (uint32_t)((r * LDA + lc) * 2);                         \
            CP16(st + 0 * G_AS * 2 + so, Ahi + ga);                               \
            CP16(st + 1 * G_AS * 2 + so, Alo + ga);                               \
            CP16(st + 2 * G_AS * 2 + so, Bhi + gb);                               \
            CP16(st + 3 * G_AS * 2 + so, Blo + gb);                               \
        }                                                                         \
    } while (0)

    const int NK = K / 32;
    G_LOAD(0, 0);
    CP_COMMIT();

    for (int it = 0; it < NK; it++) {
        if (it + 1 < NK) G_LOAD((it + 1) & 1, (it + 1) * 32);
        CP_COMMIT();
        CP_WAIT1();
        __syncthreads();

        const uint32_t st   = sb + (uint32_t)(it & 1) * G_STAGE_B;
        const uint32_t aB   = st;
        const uint32_t alB  = st + 1 * G_AS * 2;
        const uint32_t bB   = st + 2 * G_AS * 2;
        const uint32_t blB  = st + 3 * G_AS * 2;

#pragma unroll
        for (int ks = 0; ks < 2; ks++) {
            const uint32_t kb = ks * 32;
            uint32_t bh[8], bl[8];
#pragma unroll
            for (int pr = 0; pr < 2; pr++) {
                uint32_t ba = bOff + (uint32_t)(pr * 16 * LDA * 2) + kb;
                ldsm_x4(bB + ba,  bh[pr*4+0], bh[pr*4+1], bh[pr*4+2], bh[pr*4+3]);
                ldsm_x4(blB + ba, bl[pr*4+0], bl[pr*4+1], bl[pr*4+2], bl[pr*4+3]);
            }
            uint32_t ah[4][4], al[4][4];
#pragma unroll
            for (int mt = 0; mt < 4; mt++) {
                uint32_t aa = aOff + (uint32_t)(mt * 16 * LDA * 2) + kb;
                ldsm_x4(aB + aa,  ah[mt][0], ah[mt][1], ah[mt][2], ah[mt][3]);
                ldsm_x4(alB + aa, al[mt][0], al[mt][1], al[mt][2], al[mt][3]);
            }
#pragma unroll
            for (int mt = 0; mt < 4; mt++) {
#pragma unroll
                for (int nt = 0; nt < 4; nt++) {
                    const int pr = nt >> 1, hf = (nt & 1) * 2;
                    uint32_t b0h = bh[pr*4 + hf], b1h = bh[pr*4 + hf + 1];
                    uint32_t b0l = bl[pr*4 + hf], b1l = bl[pr*4 + hf + 1];
                    mma16816(acc[mt][nt], ah[mt][0], ah[mt][1], ah[mt][2], ah[mt][3], b0h, b1h);
                    mma16816(acc[mt][nt], al[mt][0], al[mt][1], al[mt][2], al[mt][3], b0h, b1h);
                    mma16816(acc[mt][nt], ah[mt][0], ah[mt][1], ah[mt][2], ah[mt][3], b0l, b1l);
                }
            }
        }
        __syncthreads();
    }

    const bool single = (Cl == nullptr);
#pragma unroll
    for (int mt = 0; mt < 4; mt++) {
#pragma unroll
        for (int nt = 0; nt < 4; nt++) {
            int row = bm + wm + mt * 16 + (lane >> 2);
            int col = bn + wn + nt * 8 + (lane & 3) * 2;
            float2 bvv = *(const float2*)&bias[col];
            float v0x = (acc[mt][nt][0] + bvv.x) * oscale, v0y = (acc[mt][nt][1] + bvv.y) * oscale;
            float v1x = (acc[mt][nt][2] + bvv.x) * oscale, v1y = (acc[mt][nt][3] + bvv.y) * oscale;
            if (OUT16) {
                if (single) {
                    *(uint32_t*)&Ch[(size_t)row * N + col]       = pack_h2(v0x, v0y);
                    *(uint32_t*)&Ch[(size_t)(row + 8) * N + col] = pack_h2(v1x, v1y);
                } else {
                    uint32_t h0, l0, h1, l1;
                    pack2_hilo(v0x, v0y, h0, l0);
                    pack2_hilo(v1x, v1y, h1, l1);
                    *(uint32_t*)&Ch[(size_t)row * N + col] = h0;
                    *(uint32_t*)&Cl[(size_t)row * N + col] = l0;
                    *(uint32_t*)&Ch[(size_t)(row + 8) * N + col] = h1;
                    *(uint32_t*)&Cl[(size_t)(row + 8) * N + col] = l1;
                }
            } else {
                *(float2*)&C[(size_t)row * N + col] = make_float2(v0x, v0y);
                *(float2*)&C[(size_t)(row + 8) * N + col] = make_float2(v1x, v1y);
            }
        }
    }
}

// ============================================================
// Tensor-core flash ConsMax attention.
// K single fp16, Q hi/lo (QK = 2 MMAs, exact vs rounded K).
// P single fp16, V hi/lo (PV = 2 MMAs, error only from P rounding).
// 128 q-rows/CTA, 8 warps, Bc=64, cp.async double-buffered.
// ============================================================
#define LDV 72
#define A_AS (64 * LDV)
#define A_STAGE_B (3 * A_AS * 2)            // Kh, Vh, Vl
#define A_MASK_OFF (2 * A_STAGE_B)
#define A_SMEM_B (A_MASK_OFF + 2 * 256)

__global__ __launch_bounds__(256) void consmax_attn_mma(
    const __half* __restrict__ Qh, const __half* __restrict__ Ql,
    const __half* __restrict__ Kh,
    const __half* __restrict__ Vh, const __half* __restrict__ Vl,
    const float* __restrict__ mask, const float* __restrict__ gamma,
    __half* __restrict__ Ch, __half* __restrict__ Cl)
{
    extern __shared__ char smem[];
    const uint32_t sb = smem_u32(smem);

    const int qb = blockIdx.x, h = blockIdx.y, b = blockIdx.z;
    const int t = threadIdx.x, lane = t & 31, w = t >> 5;
    const int row0 = b * S_ + qb * 128;

    // ---- Q fragments straight from global (A-frag layout) ----
    uint32_t qh[4][4], ql[4][4];
    {
        const int fr = lane >> 2;
        const int fc = (lane & 3) * 2;
        const size_t base = (size_t)(row0 + w * 16 + fr) * HID_ + h * HD_ + fc;
#pragma unroll
        for (int ks = 0; ks < 4; ks++) {
            const size_t g = base + ks * 16;
            qh[ks][0] = *(const uint32_t*)(Qh + g);
            qh[ks][1] = *(const uint32_t*)(Qh + g + 8 * HID_);
            qh[ks][2] = *(const uint32_t*)(Qh + g + 8);
            qh[ks][3] = *(const uint32_t*)(Qh + g + 8 * HID_ + 8);
            ql[ks][0] = *(const uint32_t*)(Ql + g);
            ql[ks][1] = *(const uint32_t*)(Ql + g + 8 * HID_);
            ql[ks][2] = *(const uint32_t*)(Ql + g + 8);
            ql[ks][3] = *(const uint32_t*)(Ql + g + 8 * HID_ + 8);
        }
    }

    float m0 = -1e30f, m1 = -1e30f;
    float O[8][4];
#pragma unroll
    for (int nt = 0; nt < 8; nt++)
#pragma unroll
        for (int r = 0; r < 4; r++) O[nt][r] = 0.0f;

#define A_LOAD(s, j0) do {                                                        \
        uint32_t st = sb + (uint32_t)(s) * A_STAGE_B;                             \
        _Pragma("unroll")                                                         \
        for (int i2 = 0; i2 < 2; i2++) {                                          \
            int u = t + 256 * i2;                                                 \
            int r = u >> 3, seg = u & 7;                                          \
            const size_t g = (size_t)(b * S_ + (j0) + r) * HID_ + h * HD_ + seg * 8; \
            uint32_t so = (uint32_t)((r * LDV + seg * 8) * 2);                    \
            CP16(st + 0 * A_AS * 2 + so, Kh + g);                                 \
            CP16(st + 1 * A_AS * 2 + so, Vh + g);                                 \
            CP16(st + 2 * A_AS * 2 + so, Vl + g);                                 \
        }                                                                         \
        if (t < 16)                                                               \
            CP16(sb + A_MASK_OFF + (uint32_t)(s) * 256 + t * 16,                  \
                 mask + (size_t)b * S_ + (j0) + t * 4);                           \
    } while (0)

    const int NCH = S_ / 64;
    A_LOAD(0, 0);
    CP_COMMIT();

    for (int it = 0; it < NCH; it++) {
        if (it + 1 < NCH) A_LOAD((it + 1) & 1, (it + 1) * 64);
        CP_COMMIT();
        CP_WAIT1();
        __syncthreads();

        const uint32_t st  = sb + (uint32_t)(it & 1) * A_STAGE_B;
        const uint32_t khB = st;
        const uint32_t vhB = st + 1 * A_AS * 2;
        const uint32_t vlB = st + 2 * A_AS * 2;
        const float* smask = (const float*)(smem + A_MASK_OFF + (it & 1) * 256);

        // ---- S = Q K^T (2 MMAs: Qh*K + Ql*K) ----
        float sc[8][4];
#pragma unroll
        for (int nt = 0; nt < 8; nt++)
#pragma unroll
            for (int r = 0; r < 4; r++) sc[nt][r] = 0.0f;

#pragma unroll
        for (int ks = 0; ks < 4; ks++) {
            uint32_t bh[4][4];
#pragma unroll
            for (int nb = 0; nb < 4; nb++) {
                uint32_t addr = (uint32_t)(((nb * 16 + (lane >> 4) * 8 + (lane & 7)) * LDV
                                            + ks * 16 + ((lane >> 3) & 1) * 8) * 2);
                ldsm_x4(khB + addr, bh[nb][0], bh[nb][1], bh[nb][2], bh[nb][3]);
            }
#pragma unroll
            for (int nb = 0; nb < 4; nb++) {
                mma16816(sc[2*nb],   qh[ks][0], qh[ks][1], qh[ks][2], qh[ks][3], bh[nb][0], bh[nb][1]);
                mma16816(sc[2*nb],   ql[ks][0], ql[ks][1], ql[ks][2], ql[ks][3], bh[nb][0], bh[nb][1]);
                mma16816(sc[2*nb+1], qh[ks][0], qh[ks][1], qh[ks][2], qh[ks][3], bh[nb][2], bh[nb][3]);
                mma16816(sc[2*nb+1], ql[ks][0], ql[ks][1], ql[ks][2], ql[ks][3], bh[nb][2], bh[nb][3]);
            }
        }

        // ---- mask + running rowmax ----
        float mn0 = m0, mn1 = m1;
#pragma unroll
        for (int nt = 0; nt < 8; nt++) {
            int col = nt * 8 + (lane & 3) * 2;
            float ma = smask[col], mb2 = smask[col + 1];
            sc[nt][0] += ma; sc[nt][1] += mb2;
            sc[nt][2] += ma; sc[nt][3] += mb2;
            mn0 = fmaxf(mn0, fmaxf(sc[nt][0], sc[nt][1]));
            mn1 = fmaxf(mn1, fmaxf(sc[nt][2], sc[nt][3]));
        }
        mn0 = fmaxf(mn0, __shfl_xor_sync(0xffffffffu, mn0, 1));
        mn0 = fmaxf(mn0, __shfl_xor_sync(0xffffffffu, mn0, 2));
        mn1 = fmaxf(mn1, __shfl_xor_sync(0xffffffffu, mn1, 1));
        mn1 = fmaxf(mn1, __shfl_xor_sync(0xffffffffu, mn1, 2));
        float f0 = __expf(m0 - mn0), f1 = __expf(m1 - mn1);
        m0 = mn0; m1 = mn1;

        // ---- P = exp(s - m) as single fp16 A-frags ----
        uint32_t pa[4][4];
#pragma unroll
        for (int ks = 0; ks < 4; ks++) {
            pa[ks][0] = pack_h2(__expf(sc[2*ks][0] - m0),   __expf(sc[2*ks][1] - m0));
            pa[ks][1] = pack_h2(__expf(sc[2*ks][2] - m1),   __expf(sc[2*ks][3] - m1));
            pa[ks][2] = pack_h2(__expf(sc[2*ks+1][0] - m0), __expf(sc[2*ks+1][1] - m0));
            pa[ks][3] = pack_h2(__expf(sc[2*ks+1][2] - m1), __expf(sc[2*ks+1][3] - m1));
        }

        // ---- rescale O ----
#pragma unroll
        for (int nt = 0; nt < 8; nt++) {
            O[nt][0] *= f0; O[nt][1] *= f0; O[nt][2] *= f1; O[nt][3] *= f1;
        }

        // ---- O += P (Vh + Vl)  (2 MMAs per tile) ----
#pragma unroll
        for (int ks = 0; ks < 4; ks++) {
            uint32_t vh[4][4], vl[4][4];
#pragma unroll
            for (int db = 0; db < 4; db++) {
                uint32_t addr = (uint32_t)(((ks * 16 + ((lane >> 3) & 1) * 8 + (lane & 7)) * LDV
                                            + db * 16 + (lane >> 4) * 8) * 2);
                ldsm_x4_trans(vhB + addr, vh[db][0], vh[db][1], vh[db][2], vh[db][3]);
                ldsm_x4_trans(vlB + addr, vl[db][0], vl[db][1], vl[db][2], vl[db][3]);
            }
#pragma unroll
            for (int db = 0; db < 4; db++) {
                mma16816(O[2*db],   pa[ks][0], pa[ks][1], pa[ks][2], pa[ks][3], vh[db][0], vh[db][1]);
                mma16816(O[2*db],   pa[ks][0], pa[ks][1], pa[ks][2], pa[ks][3], vl[db][0], vl[db][1]);
                mma16816(O[2*db+1], pa[ks][0], pa[ks][1], pa[ks][2], pa[ks][3], vh[db][2], vh[db][3]);
                mma16816(O[2*db+1], pa[ks][0], pa[ks][1], pa[ks][2], pa[ks][3], vl[db][2], vl[db][3]);
            }
        }
        __syncthreads();
    }

    // ---- epilogue: O/gamma -> fp16 hi/lo ----
    const float ig = 1.0f / gamma[0];
#pragma unroll
    for (int nt = 0; nt < 8; nt++) {
        int r = row0 + w * 16 + (lane >> 2);
        int col = h * HD_ + nt * 8 + (lane & 3) * 2;
        uint32_t h0, l0, h1, l1;
        pack2_hilo(O[nt][0] * ig, O[nt][1] * ig, h0, l0);
        pack2_hilo(O[nt][2] * ig, O[nt][3] * ig, h1, l1);
        *(uint32_t*)&Ch[(size_t)r * HID_ + col] = h0;
        *(uint32_t*)&Cl[(size_t)r * HID_ + col] = l0;
        *(uint32_t*)&Ch[(size_t)(r + 8) * HID_ + col] = h1;
        *(uint32_t*)&Cl[(size_t)(r + 8) * HID_ + col] = l1;
    }
}

// ============================================================
// Launch
// ============================================================
extern "C" void kernel_launch(void* const* d_in, const int* in_sizes, int n_in,
                              void* d_out, int out_size)
{
    (void)in_sizes; (void)n_in; (void)out_size;
    const float* X    = (const float*)d_in[0];
    const float* mask = (const float*)d_in[1];
    const float* Wq   = (const float*)d_in[2];
    const float* bq   = (const float*)d_in[3];
    const float* Wk   = (const float*)d_in[4];
    const float* bk   = (const float*)d_in[5];
    const float* Wv   = (const float*)d_in[6];
    const float* bv   = (const float*)d_in[7];
    const float* Wo   = (const float*)d_in[8];
    const float* bo   = (const float*)d_in[9];
    const float* gamma = (const float*)d_in[11];   // beta (d_in[10]) cancels exactly
    float* out = (float*)d_out;

    __half *xhi, *xlo, *whi, *wlo, *qhp, *qlp, *khp, *vhp, *vlp, *chp, *clp;
    cudaGetSymbolAddress((void**)&xhi, g_Xhi);
    cudaGetSymbolAddress((void**)&xlo, g_Xlo);
    cudaGetSymbolAddress((void**)&whi, g_Whi);
    cudaGetSymbolAddress((void**)&wlo, g_Wlo);
    cudaGetSymbolAddress((void**)&qhp, g_Qh);
    cudaGetSymbolAddress((void**)&qlp, g_Ql);
    cudaGetSymbolAddress((void**)&khp, g_Kh);
    cudaGetSymbolAddress((void**)&vhp, g_Vh);
    cudaGetSymbolAddress((void**)&vlp, g_Vl);
    cudaGetSymbolAddress((void**)&chp, g_Ch);
    cudaGetSymbolAddress((void**)&clp, g_Cl);

    cudaFuncSetAttribute(gemm_mma_f16x3<true>,  cudaFuncAttributeMaxDynamicSharedMemorySize, G_SMEM_B);
    cudaFuncSetAttribute(gemm_mma_f16x3<false>, cudaFuncAttributeMaxDynamicSharedMemorySize, G_SMEM_B);
    cudaFuncSetAttribute(consmax_attn_mma,      cudaFuncAttributeMaxDynamicSharedMemorySize, A_SMEM_B);

    cvt_split<<<(MTOT * HID_ / 4 + 255) / 256, 256>>>(X, xhi, xlo, MTOT * HID_ / 4);
    cvt_split4<<<(4 * WN_ / 4) / 256, 256>>>(Wq, Wk, Wv, Wo, whi, wlo);

    // fused QKV projection: z = 0(Q, x1/8, hi/lo), 1(K, single fp16), 2(V, hi/lo)
    dim3 gq(HID_ / 128, MTOT / 128, 3);
    gemm_mma_f16x3<true><<<gq, 256, G_SMEM_B>>>(xhi, xlo, whi, wlo,
                                                bq, bk, bv, nullptr,
                                                qhp, qlp, khp, nullptr, vhp, vlp,
                                                MTOT, HID_, HID_, 0.125f);

    dim3 ga(S_ / 128, NH_, B_);        // (16, 16, 2)
    consmax_attn_mma<<<ga, 256, A_SMEM_B>>>(qhp, qlp, khp, vhp, vlp, mask, gamma, chp, clp);

    dim3 go(HID_ / 128, MTOT / 128, 1);
    gemm_mma_f16x3<false><<<go, 256, G_SMEM_B>>>(chp, clp, whi + 3 * (size_t)WN_, wlo + 3 * (size_t)WN_,
                                                 bo, nullptr, nullptr,
                                                 out, nullptr, nullptr, nullptr, nullptr, nullptr, nullptr,
                                                 MTOT, HID_, HID_, 1.0f);
}

// round 9
// speedup vs baseline: 3.3407x; 1.6151x over previous
#include <cuda_runtime.h>
#include <cuda_fp16.h>
#include <math.h>
#include <stdint.h>

#define B_    2
#define S_    2048
#define HID_  1024
#define NH_   16
#define HD_   64
#define MTOT  (B_ * S_)
#define WN_   (HID_ * HID_)

// ---------------- scratch (static device allocations) ----------------
__device__ __half g_Xhi[MTOT * HID_];
__device__ __half g_Xlo[MTOT * HID_];
__device__ __half g_Wh[4 * WN_];
__device__ __half g_Q[MTOT * HID_];
__device__ __half g_K[MTOT * HID_];
__device__ __half g_V[MTOT * HID_];
__device__ __half g_Ch[MTOT * HID_];
__device__ __half g_Cl[MTOT * HID_];

// ---------------- helpers (baseline PTX only) ----------------
__device__ __forceinline__ uint32_t smem_u32(const void* p) {
    uint32_t a;
    asm("{ .reg .u64 t; cvta.to.shared.u64 t, %1; cvt.u32.u64 %0, t; }" : "=r"(a) : "l"(p));
    return a;
}
__device__ __forceinline__ void ldsm_x4(uint32_t addr, uint32_t& r0, uint32_t& r1,
                                        uint32_t& r2, uint32_t& r3) {
    asm volatile("ldmatrix.sync.aligned.m8n8.x4.shared.b16 {%0,%1,%2,%3}, [%4];"
                 : "=r"(r0), "=r"(r1), "=r"(r2), "=r"(r3) : "r"(addr));
}
__device__ __forceinline__ void ldsm_x4_trans(uint32_t addr, uint32_t& r0, uint32_t& r1,
                                              uint32_t& r2, uint32_t& r3) {
    asm volatile("ldmatrix.sync.aligned.m8n8.x4.trans.shared.b16 {%0,%1,%2,%3}, [%4];"
                 : "=r"(r0), "=r"(r1), "=r"(r2), "=r"(r3) : "r"(addr));
}
__device__ __forceinline__ void mma16816(float* c, uint32_t a0, uint32_t a1,
                                         uint32_t a2, uint32_t a3,
                                         uint32_t b0, uint32_t b1) {
    asm volatile(
        "mma.sync.aligned.m16n8k16.row.col.f32.f16.f16.f32 "
        "{%0,%1,%2,%3}, {%4,%5,%6,%7}, {%8,%9}, {%0,%1,%2,%3};"
        : "+f"(c[0]), "+f"(c[1]), "+f"(c[2]), "+f"(c[3])
        : "r"(a0), "r"(a1), "r"(a2), "r"(a3), "r"(b0), "r"(b1));
}
__device__ __forceinline__ uint32_t pack_h2(float a, float b) {
    __half2 h = __floats2half2_rn(a, b);
    return *(uint32_t*)&h;
}
__device__ __forceinline__ void pack2_hilo(float a, float b, uint32_t& hi, uint32_t& lo) {
    __half2 h = __floats2half2_rn(a, b);
    float2 hf = __half22float2(h);
    __half2 l = __floats2half2_rn(a - hf.x, b - hf.y);
    hi = *(uint32_t*)&h;
    lo = *(uint32_t*)&l;
}
#define CP16(dst, src) \
    asm volatile("cp.async.cg.shared.global [%0], [%1], 16;" :: "r"(dst), "l"(src))
#define CP_COMMIT() asm volatile("cp.async.commit_group;")
#define CP_WAIT1()  asm volatile("cp.async.wait_group 1;")

// ---------------- converters ----------------
__global__ __launch_bounds__(256) void cvt_split(
    const float* __restrict__ in, __half* __restrict__ hi,
    __half* __restrict__ lo, int n4)
{
    int i = blockIdx.x * blockDim.x + threadIdx.x;
    if (i >= n4) return;
    float4 v = ((const float4*)in)[i];
    uint32_t h0, l0, h1, l1;
    pack2_hilo(v.x, v.y, h0, l0);
    pack2_hilo(v.z, v.w, h1, l1);
    ((uint2*)hi)[i] = make_uint2(h0, h1);
    ((uint2*)lo)[i] = make_uint2(l0, l1);
}

// fused single-fp16 conversion for all 4 weights
__global__ __launch_bounds__(256) void cvt_h4(
    const float* __restrict__ w0, const float* __restrict__ w1,
    const float* __restrict__ w2, const float* __restrict__ w3,
    __half* __restrict__ wh)
{
    const int n4per = WN_ / 4;
    int i = blockIdx.x * blockDim.x + threadIdx.x;
    int sel = i / n4per;
    int j   = i - sel * n4per;
    const float* src = sel == 0 ? w0 : (sel == 1 ? w1 : (sel == 2 ? w2 : w3));
    float4 v = ((const float4*)src)[j];
    ((uint2*)wh)[i] = make_uint2(pack_h2(v.x, v.y), pack_h2(v.z, v.w));
}

// ============================================================
// Tensor-core GEMM, cp.async double-buffered, fp16 2-term:
// C = ((Ahi + Alo) @ Wh^T + bias) * oscale
// grid.z selects among up to 3 (W, bias, dest) sets.
// OUT16: single-fp16 output; else fp32.
// ============================================================
#define LDA 40
#define G_AS (128 * LDA)
#define G_STAGE_B (3 * G_AS * 2)
#define G_SMEM_B (2 * G_STAGE_B)

template<bool OUT16>
__global__ __launch_bounds__(256) void gemm_mma_f16x2(
    const __half* __restrict__ Ahi, const __half* __restrict__ Alo,
    const __half* __restrict__ Whb,
    const float* __restrict__ bias0, const float* __restrict__ bias1,
    const float* __restrict__ bias2,
    float* __restrict__ C,
    __half* __restrict__ C0, __half* __restrict__ C1, __half* __restrict__ C2,
    int M, int N, int K, float osc0)
{
    extern __shared__ char smem[];
    const uint32_t sb = smem_u32(smem);

    const int z = blockIdx.z;
    const __half* Bh = Whb + (size_t)z * WN_;
    const float* bias = z == 0 ? bias0 : (z == 1 ? bias1 : bias2);
    __half* Cd = z == 0 ? C0 : (z == 1 ? C1 : C2);
    const float oscale = z == 0 ? osc0 : 1.0f;

    const int t    = threadIdx.x;
    const int lane = t & 31;
    const int wid  = t >> 5;
    const int wm   = (wid & 1) * 64;
    const int wn   = (wid >> 1) * 32;
    const int bm   = blockIdx.y * 128;
    const int bn   = blockIdx.x * 128;

    float acc[4][4][4];
#pragma unroll
    for (int i = 0; i < 4; i++)
#pragma unroll
        for (int j = 0; j < 4; j++)
#pragma unroll
            for (int r = 0; r < 4; r++) acc[i][j][r] = 0.0f;

    const int lr = t >> 2;
    const int lc = (t & 3) * 8;

    const uint32_t aOff = (uint32_t)(((wm + (lane & 15)) * LDA + (lane >> 4) * 8) * 2);
    const uint32_t bOff = (uint32_t)(((wn + (lane >> 4) * 8 + (lane & 7)) * LDA + ((lane >> 3) & 1) * 8) * 2);

#define G_LOAD(s, k0) do {                                                        \
        uint32_t st = sb + (uint32_t)(s) * G_STAGE_B;                             \
        _Pragma("unroll")                                                         \
        for (int bch = 0; bch < 2; bch++) {                                       \
            int r = lr + bch * 64;                                                \
            size_t ga = (size_t)(bm + r) * K + (k0) + lc;                         \
            size_t gb = (size_t)(bn + r) * K + (k0) + lc;                         \
            uint32_t so = (uint32_t)((r * LDA + lc) * 2);                         \
            CP16(st + 0 * G_AS * 2 + so, Ahi + ga);                               \
            CP16(st + 1 * G_AS * 2 + so, Alo + ga);                               \
            CP16(st + 2 * G_AS * 2 + so, Bh + gb);                                \
        }                                                                         \
    } while (0)

    const int NK = K / 32;
    G_LOAD(0, 0);
    CP_COMMIT();

    for (int it = 0; it < NK; it++) {
        if (it + 1 < NK) G_LOAD((it + 1) & 1, (it + 1) * 32);
        CP_COMMIT();
        CP_WAIT1();
        __syncthreads();

        const uint32_t st   = sb + (uint32_t)(it & 1) * G_STAGE_B;
        const uint32_t aB   = st;
        const uint32_t alB  = st + 1 * G_AS * 2;
        const uint32_t bB   = st + 2 * G_AS * 2;

#pragma unroll
        for (int ks = 0; ks < 2; ks++) {
            const uint32_t kb = ks * 32;
            uint32_t bh[8];
#pragma unroll
            for (int pr = 0; pr < 2; pr++) {
                uint32_t ba = bOff + (uint32_t)(pr * 16 * LDA * 2) + kb;
                ldsm_x4(bB + ba, bh[pr*4+0], bh[pr*4+1], bh[pr*4+2], bh[pr*4+3]);
            }
            uint32_t ah[4][4], al[4][4];
#pragma unroll
            for (int mt = 0; mt < 4; mt++) {
                uint32_t aa = aOff + (uint32_t)(mt * 16 * LDA * 2) + kb;
                ldsm_x4(aB + aa,  ah[mt][0], ah[mt][1], ah[mt][2], ah[mt][3]);
                ldsm_x4(alB + aa, al[mt][0], al[mt][1], al[mt][2], al[mt][3]);
            }
#pragma unroll
            for (int mt = 0; mt < 4; mt++) {
#pragma unroll
                for (int nt = 0; nt < 4; nt++) {
                    const int pr = nt >> 1, hf = (nt & 1) * 2;
                    uint32_t b0 = bh[pr*4 + hf], b1 = bh[pr*4 + hf + 1];
                    mma16816(acc[mt][nt], ah[mt][0], ah[mt][1], ah[mt][2], ah[mt][3], b0, b1);
                    mma16816(acc[mt][nt], al[mt][0], al[mt][1], al[mt][2], al[mt][3], b0, b1);
                }
            }
        }
        __syncthreads();
    }

#pragma unroll
    for (int mt = 0; mt < 4; mt++) {
#pragma unroll
        for (int nt = 0; nt < 4; nt++) {
            int row = bm + wm + mt * 16 + (lane >> 2);
            int col = bn + wn + nt * 8 + (lane & 3) * 2;
            float2 bvv = *(const float2*)&bias[col];
            float v0x = (acc[mt][nt][0] + bvv.x) * oscale, v0y = (acc[mt][nt][1] + bvv.y) * oscale;
            float v1x = (acc[mt][nt][2] + bvv.x) * oscale, v1y = (acc[mt][nt][3] + bvv.y) * oscale;
            if (OUT16) {
                *(uint32_t*)&Cd[(size_t)row * N + col]       = pack_h2(v0x, v0y);
                *(uint32_t*)&Cd[(size_t)(row + 8) * N + col] = pack_h2(v1x, v1y);
            } else {
                *(float2*)&C[(size_t)row * N + col] = make_float2(v0x, v0y);
                *(float2*)&C[(size_t)(row + 8) * N + col] = make_float2(v1x, v1y);
            }
        }
    }
}

// ============================================================
// Tensor-core flash ConsMax attention, fully single fp16.
// QK^T = 1 MMA, PV = 1 MMA. 128 q-rows/CTA, 8 warps, Bc=64.
// Q pre-scaled by 1/8. Emits C as fp16 hi/lo.
// ============================================================
#define LDV 72
#define A_AS (64 * LDV)
#define A_STAGE_B (2 * A_AS * 2)            // K, V
#define A_MASK_OFF (2 * A_STAGE_B)
#define A_SMEM_B (A_MASK_OFF + 2 * 256)

__global__ __launch_bounds__(256) void consmax_attn_mma(
    const __half* __restrict__ Q, const __half* __restrict__ K,
    const __half* __restrict__ V,
    const float* __restrict__ mask, const float* __restrict__ gamma,
    __half* __restrict__ Ch, __half* __restrict__ Cl)
{
    extern __shared__ char smem[];
    const uint32_t sb = smem_u32(smem);

    const int qb = blockIdx.x, h = blockIdx.y, b = blockIdx.z;
    const int t = threadIdx.x, lane = t & 31, w = t >> 5;
    const int row0 = b * S_ + qb * 128;

    // ---- Q fragments straight from global (A-frag layout) ----
    uint32_t qf[4][4];
    {
        const int fr = lane >> 2;
        const int fc = (lane & 3) * 2;
        const size_t base = (size_t)(row0 + w * 16 + fr) * HID_ + h * HD_ + fc;
#pragma unroll
        for (int ks = 0; ks < 4; ks++) {
            const size_t g = base + ks * 16;
            qf[ks][0] = *(const uint32_t*)(Q + g);
            qf[ks][1] = *(const uint32_t*)(Q + g + 8 * HID_);
            qf[ks][2] = *(const uint32_t*)(Q + g + 8);
            qf[ks][3] = *(const uint32_t*)(Q + g + 8 * HID_ + 8);
        }
    }

    float m0 = -1e30f, m1 = -1e30f;
    float O[8][4];
#pragma unroll
    for (int nt = 0; nt < 8; nt++)
#pragma unroll
        for (int r = 0; r < 4; r++) O[nt][r] = 0.0f;

#define A_LOAD(s, j0) do {                                                        \
        uint32_t st = sb + (uint32_t)(s) * A_STAGE_B;                             \
        _Pragma("unroll")                                                         \
        for (int i2 = 0; i2 < 2; i2++) {                                          \
            int u = t + 256 * i2;                                                 \
            int r = u >> 3, seg = u & 7;                                          \
            const size_t g = (size_t)(b * S_ + (j0) + r) * HID_ + h * HD_ + seg * 8; \
            uint32_t so = (uint32_t)((r * LDV + seg * 8) * 2);                    \
            CP16(st + 0 * A_AS * 2 + so, K + g);                                  \
            CP16(st + 1 * A_AS * 2 + so, V + g);                                  \
        }                                                                         \
        if (t < 16)                                                               \
            CP16(sb + A_MASK_OFF + (uint32_t)(s) * 256 + t * 16,                  \
                 mask + (size_t)b * S_ + (j0) + t * 4);                           \
    } while (0)

    const int NCH = S_ / 64;
    A_LOAD(0, 0);
    CP_COMMIT();

    for (int it = 0; it < NCH; it++) {
        if (it + 1 < NCH) A_LOAD((it + 1) & 1, (it + 1) * 64);
        CP_COMMIT();
        CP_WAIT1();
        __syncthreads();

        const uint32_t st  = sb + (uint32_t)(it & 1) * A_STAGE_B;
        const uint32_t kB  = st;
        const uint32_t vB  = st + 1 * A_AS * 2;
        const float* smask = (const float*)(smem + A_MASK_OFF + (it & 1) * 256);

        // ---- S = Q K^T (1 MMA per tile) ----
        float sc[8][4];
#pragma unroll
        for (int nt = 0; nt < 8; nt++)
#pragma unroll
            for (int r = 0; r < 4; r++) sc[nt][r] = 0.0f;

#pragma unroll
        for (int ks = 0; ks < 4; ks++) {
            uint32_t bh[4][4];
#pragma unroll
            for (int nb = 0; nb < 4; nb++) {
                uint32_t addr = (uint32_t)(((nb * 16 + (lane >> 4) * 8 + (lane & 7)) * LDV
                                            + ks * 16 + ((lane >> 3) & 1) * 8) * 2);
                ldsm_x4(kB + addr, bh[nb][0], bh[nb][1], bh[nb][2], bh[nb][3]);
            }
#pragma unroll
            for (int nb = 0; nb < 4; nb++) {
                mma16816(sc[2*nb],   qf[ks][0], qf[ks][1], qf[ks][2], qf[ks][3], bh[nb][0], bh[nb][1]);
                mma16816(sc[2*nb+1], qf[ks][0], qf[ks][1], qf[ks][2], qf[ks][3], bh[nb][2], bh[nb][3]);
            }
        }

        // ---- mask + running rowmax ----
        float mn0 = m0, mn1 = m1;
#pragma unroll
        for (int nt = 0; nt < 8; nt++) {
            int col = nt * 8 + (lane & 3) * 2;
            float ma = smask[col], mb2 = smask[col + 1];
            sc[nt][0] += ma; sc[nt][1] += mb2;
            sc[nt][2] += ma; sc[nt][3] += mb2;
            mn0 = fmaxf(mn0, fmaxf(sc[nt][0], sc[nt][1]));
            mn1 = fmaxf(mn1, fmaxf(sc[nt][2], sc[nt][3]));
        }
        mn0 = fmaxf(mn0, __shfl_xor_sync(0xffffffffu, mn0, 1));
        mn0 = fmaxf(mn0, __shfl_xor_sync(0xffffffffu, mn0, 2));
        mn1 = fmaxf(mn1, __shfl_xor_sync(0xffffffffu, mn1, 1));
        mn1 = fmaxf(mn1, __shfl_xor_sync(0xffffffffu, mn1, 2));
        float f0 = __expf(m0 - mn0), f1 = __expf(m1 - mn1);
        m0 = mn0; m1 = mn1;

        // ---- P = exp(s - m) as single fp16 A-frags ----
        uint32_t pa[4][4];
#pragma unroll
        for (int ks = 0; ks < 4; ks++) {
            pa[ks][0] = pack_h2(__expf(sc[2*ks][0] - m0),   __expf(sc[2*ks][1] - m0));
            pa[ks][1] = pack_h2(__expf(sc[2*ks][2] - m1),   __expf(sc[2*ks][3] - m1));
            pa[ks][2] = pack_h2(__expf(sc[2*ks+1][0] - m0), __expf(sc[2*ks+1][1] - m0));
            pa[ks][3] = pack_h2(__expf(sc[2*ks+1][2] - m1), __expf(sc[2*ks+1][3] - m1));
        }

        // ---- rescale O ----
#pragma unroll
        for (int nt = 0; nt < 8; nt++) {
            O[nt][0] *= f0; O[nt][1] *= f0; O[nt][2] *= f1; O[nt][3] *= f1;
        }

        // ---- O += P V (1 MMA per tile) ----
#pragma unroll
        for (int ks = 0; ks < 4; ks++) {
            uint32_t vf[4][4];
#pragma unroll
            for (int db = 0; db < 4; db++) {
                uint32_t addr = (uint32_t)(((ks * 16 + ((lane >> 3) & 1) * 8 + (lane & 7)) * LDV
                                            + db * 16 + (lane >> 4) * 8) * 2);
                ldsm_x4_trans(vB + addr, vf[db][0], vf[db][1], vf[db][2], vf[db][3]);
            }
#pragma unroll
            for (int db = 0; db < 4; db++) {
                mma16816(O[2*db],   pa[ks][0], pa[ks][1], pa[ks][2], pa[ks][3], vf[db][0], vf[db][1]);
                mma16816(O[2*db+1], pa[ks][0], pa[ks][1], pa[ks][2], pa[ks][3], vf[db][2], vf[db][3]);
            }
        }
        __syncthreads();
    }

    // ---- epilogue: O/gamma -> fp16 hi/lo ----
    const float ig = 1.0f / gamma[0];
#pragma unroll
    for (int nt = 0; nt < 8; nt++) {
        int r = row0 + w * 16 + (lane >> 2);
        int col = h * HD_ + nt * 8 + (lane & 3) * 2;
        uint32_t h0, l0, h1, l1;
        pack2_hilo(O[nt][0] * ig, O[nt][1] * ig, h0, l0);
        pack2_hilo(O[nt][2] * ig, O[nt][3] * ig, h1, l1);
        *(uint32_t*)&Ch[(size_t)r * HID_ + col] = h0;
        *(uint32_t*)&Cl[(size_t)r * HID_ + col] = l0;
        *(uint32_t*)&Ch[(size_t)(r + 8) * HID_ + col] = h1;
        *(uint32_t*)&Cl[(size_t)(r + 8) * HID_ + col] = l1;
    }
}

// ============================================================
// Launch
// ============================================================
extern "C" void kernel_launch(void* const* d_in, const int* in_sizes, int n_in,
                              void* d_out, int out_size)
{
    (void)in_sizes; (void)n_in; (void)out_size;
    const float* X    = (const float*)d_in[0];
    const float* mask = (const float*)d_in[1];
    const float* Wq   = (const float*)d_in[2];
    const float* bq   = (const float*)d_in[3];
    const float* Wk   = (const float*)d_in[4];
    const float* bk   = (const float*)d_in[5];
    const float* Wv   = (const float*)d_in[6];
    const float* bv   = (const float*)d_in[7];
    const float* Wo   = (const float*)d_in[8];
    const float* bo   = (const float*)d_in[9];
    const float* gamma = (const float*)d_in[11];   // beta (d_in[10]) cancels exactly
    float* out = (float*)d_out;

    __half *xhi, *xlo, *wh, *qp, *kp, *vp, *chp, *clp;
    cudaGetSymbolAddress((void**)&xhi, g_Xhi);
    cudaGetSymbolAddress((void**)&xlo, g_Xlo);
    cudaGetSymbolAddress((void**)&wh,  g_Wh);
    cudaGetSymbolAddress((void**)&qp,  g_Q);
    cudaGetSymbolAddress((void**)&kp,  g_K);
    cudaGetSymbolAddress((void**)&vp,  g_V);
    cudaGetSymbolAddress((void**)&chp, g_Ch);
    cudaGetSymbolAddress((void**)&clp, g_Cl);

    cudaFuncSetAttribute(gemm_mma_f16x2<true>,  cudaFuncAttributeMaxDynamicSharedMemorySize, G_SMEM_B);
    cudaFuncSetAttribute(gemm_mma_f16x2<false>, cudaFuncAttributeMaxDynamicSharedMemorySize, G_SMEM_B);
    cudaFuncSetAttribute(consmax_attn_mma,      cudaFuncAttributeMaxDynamicSharedMemorySize, A_SMEM_B);

    cvt_split<<<(MTOT * HID_ / 4 + 255) / 256, 256>>>(X, xhi, xlo, MTOT * HID_ / 4);
    cvt_h4<<<(4 * WN_ / 4) / 256, 256>>>(Wq, Wk, Wv, Wo, wh);

    // fused QKV projection: z = 0(Q, x1/8), 1(K), 2(V) — single fp16 outputs
    dim3 gq(HID_ / 128, MTOT / 128, 3);
    gemm_mma_f16x2<true><<<gq, 256, G_SMEM_B>>>(xhi, xlo, wh,
                                                bq, bk, bv, nullptr,
                                                qp, kp, vp,
                                                MTOT, HID_, HID_, 0.125f);

    dim3 ga(S_ / 128, NH_, B_);        // (16, 16, 2)
    consmax_attn_mma<<<ga, 256, A_SMEM_B>>>(qp, kp, vp, mask, gamma, chp, clp);

    dim3 go(HID_ / 128, MTOT / 128, 1);
    gemm_mma_f16x2<false><<<go, 256, G_SMEM_B>>>(chp, clp, wh + 3 * (size_t)WN_,
                                                 bo, nullptr, nullptr,
                                                 out, nullptr, nullptr, nullptr,
                                                 MTOT, HID_, HID_, 1.0f);
}